// round 5
// baseline (speedup 1.0000x reference)
#include <cuda_runtime.h>

#define FULLMASK 0xffffffffu

// scratch (allocation-free contract: __device__ globals)
__device__ float g_s[16384];        // softmax logits, one per (b, c)
__device__ float g_hfsel[512*128];  // hf row at agent_id per b
__device__ float g_red[2];          // softmax max, sumexp

__device__ __forceinline__ float wredsum(float v){
  #pragma unroll
  for(int o=16;o;o>>=1) v += __shfl_xor_sync(FULLMASK,v,o);
  return v;
}

typedef unsigned long long u64;

__device__ __forceinline__ float2 unpack2(u64 v){
  float2 r; asm("mov.b64 {%0,%1}, %2;" : "=f"(r.x), "=f"(r.y) : "l"(v)); return r;
}
__device__ __forceinline__ void fma2(u64& d, u64 a, u64 b){
  asm("fma.rn.f32x2 %0, %1, %2, %0;" : "+l"(d) : "l"(a), "l"(b));
}

// ---- shared memory layout (floats) ----
#define OFF_W2   0        // 16384  linh_w[0] transposed+swizzled [h][k]
#define OFF_W3   16384    // 16384  linh_w[1] transposed+swizzled [h][k]
#define OFF_BASE 32768    // 4096   base[r][h]  (stage B: fc2a_b, fc2b_w)
#define OFF_A    36864    // 16384  activation tile [edge][k], 128 edges
                          //        (preamble: W1 + xj; stage B: hacc)
#define OFF_EL   53248    // 1024   e values of active edges
#define OFF_LN1G 54272    // 128
#define OFF_LN1B 54400    // 128
#define OFF_LHB  54528    // 256    linh_b
#define OFF_LHG  54784    // 256    lnh_g
#define OFF_LHBB 55040    // 256    lnh_b
#define OFF_CL   55296    // 1024   (c<<5)|r of active edges (int)
#define OFF_MISC 56320    // 96     scount[32], sstart[33]
#define SMEM_FLOATS 56416
#define SMEM_BYTES (SMEM_FLOATS*4)

__global__ __launch_bounds__(512,1)
void gnn_k1(const float* __restrict__ node_obs, const float* __restrict__ adj,
            const int* __restrict__ agent_id, const float* __restrict__ emb,
            const float* __restrict__ lin1_w, const float* __restrict__ lin1_b,
            const float* __restrict__ ln1_g, const float* __restrict__ ln1_b,
            const float* __restrict__ linh_w, const float* __restrict__ linh_b,
            const float* __restrict__ lnh_g, const float* __restrict__ lnh_b,
            const float* __restrict__ fc2a_w, const float* __restrict__ fc2a_b,
            const float* __restrict__ fc2b_w, const float* __restrict__ fc2b_b)
{
  extern __shared__ float sm[];
  float* sW2  = sm+OFF_W2;
  float* sW3  = sm+OFF_W3;
  float* base = sm+OFF_BASE;
  float* sA   = sm+OFF_A;
  float* sW1  = sm+OFF_A;          // alias: preamble only
  float* sxj  = sm+OFF_A+4096;     // alias: preamble only
  float* hacc = sm+OFF_A;          // alias: after tile loop
  float* elist= sm+OFF_EL;
  int*   clist=(int*)(sm+OFF_CL);
  int*   scount=(int*)(sm+OFF_MISC);
  int*   sstart=scount+32;         // 33 entries

  const int b=blockIdx.x, t=threadIdx.x, lane=t&31, w=t>>5;

  // ---- weights: transpose [k][h] -> [h][k] with per-row XOR swizzle ----
  // element (k,h) stored at dst[h*128 + ((k&~3)^(4*(h&7))) + (k&3)]
  {
    const float4* src=(const float4*)linh_w;
    for(int i=t;i<8192;i+=512){
      int l   = i>>12;
      int rem = i&4095;
      int k   = rem>>5;
      int h4  = (rem&31)*4;
      float4 v = src[i];
      float* dst = l? sW3 : sW2;
      int kb=k&~3, kr=k&3;
      dst[(h4+0)*128 + ((kb^(4*((h4+0)&7)))+kr)] = v.x;
      dst[(h4+1)*128 + ((kb^(4*((h4+1)&7)))+kr)] = v.y;
      dst[(h4+2)*128 + ((kb^(4*((h4+2)&7)))+kr)] = v.z;
      dst[(h4+3)*128 + ((kb^(4*((h4+3)&7)))+kr)] = v.w;
    }
    const float4* s1=(const float4*)lin1_w; float4* d1=(float4*)sW1;
    for(int i=t;i<1024;i+=512) d1[i]=s1[i];
  }
  if(t<128){ sm[OFF_LN1G+t]=ln1_g[t]; sm[OFF_LN1B+t]=ln1_b[t]; }
  if(t<256){ sm[OFF_LHB+t]=linh_b[t]; sm[OFF_LHG+t]=lnh_g[t]; sm[OFF_LHBB+t]=lnh_b[t]; }

  // xj per r: 15 feats + 16-dim entity embedding
  if(t<32){
    const int r=t;
    const float* no = node_obs + (size_t)b*512 + r*16;
    #pragma unroll
    for(int k=0;k<15;k++) sxj[r*32+k]=no[k];
    int ent=(int)no[15];
    #pragma unroll
    for(int j=0;j<16;j++) sxj[r*32+15+j]=emb[ent*16+j];
    sxj[r*32+31]=0.f;
  }
  __syncthreads();

  // per-lane layer-1 constants (grab before W1 region is overwritten)
  const float4 w1l = *(const float4*)&sW1[31*128+lane*4];

  // ---- base[r][h] = xj[r] @ W1[0:31] + b1 ----
  {
    const int h=t&127, r0=t>>7;
    for(int r=r0;r<32;r+=4){
      float acc=lin1_b[h];
      #pragma unroll
      for(int k=0;k<31;k++) acc += sxj[r*32+k]*sW1[k*128+h];
      base[r*128+h]=acc;
    }
  }

  // ---- edge compaction (c-major), per-c counts via ballot ----
  float ev2[2]; int rc2[2]; int act2[2]; int cnt=0;
  #pragma unroll
  for(int q=0;q<2;q++){
    int idx=t*2+q; int c=idx>>5; int r=idx&31;
    float v=adj[(size_t)b*1024 + r*32 + c];
    int a=(v>0.f)&&(v<1.0f);
    act2[q]=a; ev2[q]=v; rc2[q]=(c<<5)|r; cnt+=a;
  }
  unsigned b0=__ballot_sync(FULLMASK,act2[0]);
  unsigned b1=__ballot_sync(FULLMASK,act2[1]);
  if(lane==0){
    scount[2*w]  =__popc(b0&0xffffu)+__popc(b1&0xffffu);
    scount[2*w+1]=__popc(b0>>16)+__popc(b1>>16);
  }
  int x=cnt;
  #pragma unroll
  for(int o=1;o<32;o<<=1){int y=__shfl_up_sync(FULLMASK,x,o); if(lane>=o)x+=y;}
  __syncthreads();
  if(t==0){
    int run=0;
    #pragma unroll
    for(int c=0;c<32;c++){ sstart[c]=run; run+=scount[c]; }
    sstart[32]=run;
  }
  __syncthreads();
  { int pos=sstart[2*w]+x-cnt;
    #pragma unroll
    for(int q=0;q<2;q++){ if(act2[q]){ clist[pos]=rc2[q]; elist[pos]=ev2[q]; pos++; } }
  }
  const int nact=sstart[32];
  __syncthreads();   // base + edge list ready; W1/xj (alias sA) now free

  // per-lane constants
  const float4 g1  = *(const float4*)&sm[OFF_LN1G+lane*4];
  const float4 b1v = *(const float4*)&sm[OFF_LN1B+lane*4];
  const int eg = w&7;              // edge-group (16 edges)
  const int rh = w>>3;             // row-half (64 rows)
  const int rA = rh*64 + lane;     // GEMM row A
  const int rB = rA + 32;          // GEMM row B
  const int swz = 4*(lane&7);      // weight swizzle for rows ≡ lane (mod 8)
  const int c0agg = 2*w;           // this warp's 2 aggregation columns

  float agg[2][4];
  #pragma unroll
  for(int cc=0;cc<2;cc++){agg[cc][0]=0;agg[cc][1]=0;agg[cc][2]=0;agg[cc][3]=0;}

  const int nt=(nact+127)/128;
  for(int T=0;T<nt;T++){
    const int tb=T*128;
    // ---- layer 1: warp -> 8 edges, in-warp LN, write sA[e][h] ----
    #pragma unroll
    for(int j=0;j<8;j++){
      int iloc=w*8+j, gi=tb+iloc;
      int r=0; float e=0.f;
      if(gi<nact){ int rc=clist[gi]; r=rc&31; e=elist[gi]; }
      float4 bs=*(const float4*)&base[r*128+lane*4];
      float vx=fmaxf(fmaf(e,w1l.x,bs.x),0.f);
      float vy=fmaxf(fmaf(e,w1l.y,bs.y),0.f);
      float vz=fmaxf(fmaf(e,w1l.z,bs.z),0.f);
      float vw=fmaxf(fmaf(e,w1l.w,bs.w),0.f);
      float s1=wredsum(vx+vy+vz+vw);
      float s2=wredsum(vx*vx+vy*vy+vz*vz+vw*vw);
      float mu=s1*(1.f/128.f);
      float inv=rsqrtf(s2*(1.f/128.f)-mu*mu+1e-5f);
      float4 o;
      o.x=(vx-mu)*inv*g1.x+b1v.x;
      o.y=(vy-mu)*inv*g1.y+b1v.y;
      o.z=(vz-mu)*inv*g1.z+b1v.z;
      o.w=(vw-mu)*inv*g1.w+b1v.w;
      *(float4*)&sA[iloc*128 + lane*4] = o;
    }
    __syncthreads();
    // ---- two hidden layers: warp tile = 16 edges x 64 rows ----
    #pragma unroll
    for(int l=0;l<2;l++){
      const float* Wt = l? sW3 : sW2;
      u64 acc2[16][2];
      #pragma unroll
      for(int e=0;e<16;e++){ acc2[e][0]=0ull; acc2[e][1]=0ull; }
      const float* WrA=&Wt[rA*128];
      const float* WrB=&Wt[rB*128];
      const float* Ae =&sA[(eg*16)*128];
      #pragma unroll 2
      for(int kq=0;kq<32;kq++){
        const int k4=kq*4;
        const int kc=k4^swz;
        ulonglong2 wa=*(const ulonglong2*)&WrA[kc];
        ulonglong2 wb=*(const ulonglong2*)&WrB[kc];
        #pragma unroll
        for(int e=0;e<16;e++){
          ulonglong2 av=*(const ulonglong2*)&Ae[e*128 + k4];
          fma2(acc2[e][0],av.x,wa.x); fma2(acc2[e][0],av.y,wa.y);
          fma2(acc2[e][1],av.x,wb.x); fma2(acc2[e][1],av.y,wb.y);
        }
      }
      __syncthreads();   // all activation reads complete before overwrite
      float bA=sm[OFF_LHB+l*128+rA], bB=sm[OFF_LHB+l*128+rB];
      #pragma unroll
      for(int e=0;e<16;e++){
        float2 fa=unpack2(acc2[e][0]);
        float2 fb=unpack2(acc2[e][1]);
        sA[(eg*16+e)*128 + rA] = fa.x+fa.y+bA;
        sA[(eg*16+e)*128 + rB] = fb.x+fb.y+bB;
      }
      __syncthreads();
      // LN pass: warp -> 8 edges
      float4 gl =*(const float4*)&sm[OFF_LHG +l*128+lane*4];
      float4 bbl=*(const float4*)&sm[OFF_LHBB+l*128+lane*4];
      #pragma unroll
      for(int j=0;j<8;j++){
        int iloc=w*8+j;
        float4 vv=*(const float4*)&sA[iloc*128 + lane*4];
        float vx=fmaxf(vv.x,0.f), vy=fmaxf(vv.y,0.f);
        float vz=fmaxf(vv.z,0.f), vw=fmaxf(vv.w,0.f);
        float s1=wredsum(vx+vy+vz+vw);
        float s2=wredsum(vx*vx+vy*vy+vz*vz+vw*vw);
        float mu=s1*(1.f/128.f);
        float inv=rsqrtf(s2*(1.f/128.f)-mu*mu+1e-5f);
        float4 o;
        o.x=(vx-mu)*inv*gl.x+bbl.x;
        o.y=(vy-mu)*inv*gl.y+bbl.y;
        o.z=(vz-mu)*inv*gl.z+bbl.z;
        o.w=(vw-mu)*inv*gl.w+bbl.w;
        *(float4*)&sA[iloc*128 + lane*4] = o;
      }
      __syncthreads();
    }
    // ---- segmented aggregation: warp owns columns c0agg, c0agg+1 ----
    #pragma unroll
    for(int cc=0;cc<2;cc++){
      int c=c0agg+cc;
      int lo=sstart[c];   if(lo<tb) lo=tb;
      int hi=sstart[c+1]; if(hi>tb+128) hi=tb+128;
      for(int i=lo;i<hi;i++){
        float4 f=*(const float4*)&sA[(i-tb)*128 + lane*4];
        agg[cc][0]+=f.x; agg[cc][1]+=f.y; agg[cc][2]+=f.z; agg[cc][3]+=f.w;
      }
    }
    __syncthreads();   // aggregation reads done before next tile's L1 writes
  }

  // commit aggregation to smem (hacc aliases sA; tile loop is done)
  #pragma unroll
  for(int cc=0;cc<2;cc++){
    float4 o; o.x=agg[cc][0]; o.y=agg[cc][1]; o.z=agg[cc][2]; o.w=agg[cc][3];
    *(float4*)&hacc[(c0agg+cc)*128 + lane*4] = o;
  }

  // ---- stage B: s[b,c] = relu(h @ fc2a + b2a) @ fc2b + b2b ----
  __syncthreads();
  {
    const float4* s2=(const float4*)fc2a_w; float4* d2=(float4*)sW2;
    for(int i=t;i<4096;i+=512) d2[i]=s2[i];
    if(t<128){ base[t]=fc2a_b[t]; base[128+t]=fc2b_w[t]; }
  }
  __syncthreads();
  {
    float4 b2=*(const float4*)&base[lane*4];
    float4 f2=*(const float4*)&base[128+lane*4];
    float acc[2][4];
    #pragma unroll
    for(int cc=0;cc<2;cc++){acc[cc][0]=b2.x;acc[cc][1]=b2.y;acc[cc][2]=b2.z;acc[cc][3]=b2.w;}
    #pragma unroll 4
    for(int k=0;k<128;k++){
      float4 wv=*(const float4*)&sW2[k*128+lane*4];
      #pragma unroll
      for(int cc=0;cc<2;cc++){
        float a=hacc[(c0agg+cc)*128+k];
        acc[cc][0]=fmaf(a,wv.x,acc[cc][0]);
        acc[cc][1]=fmaf(a,wv.y,acc[cc][1]);
        acc[cc][2]=fmaf(a,wv.z,acc[cc][2]);
        acc[cc][3]=fmaf(a,wv.w,acc[cc][3]);
      }
    }
    float b2b=fc2b_b[0];
    #pragma unroll
    for(int cc=0;cc<2;cc++){
      float p=fmaxf(acc[cc][0],0.f)*f2.x+fmaxf(acc[cc][1],0.f)*f2.y
             +fmaxf(acc[cc][2],0.f)*f2.z+fmaxf(acc[cc][3],0.f)*f2.w;
      p=wredsum(p);
      if(lane==0) g_s[b*32+c0agg+cc]=p+b2b;
    }
  }
  // stash the hf row this batch actually uses
  if(t<128){
    int ag=agent_id[b];
    g_hfsel[b*128+t]=hacc[ag*128+t];
  }
}

// ---- global softmax reduction over 16384 logits ----
__global__ void gnn_k2(){
  __shared__ float sw[8];
  int t=threadIdx.x, lane=t&31, w=t>>5;
  float m=-3.4e38f;
  for(int i=t;i<16384;i+=256) m=fmaxf(m,g_s[i]);
  #pragma unroll
  for(int o=16;o;o>>=1) m=fmaxf(m,__shfl_xor_sync(FULLMASK,m,o));
  if(lane==0) sw[w]=m;
  __syncthreads();
  float M=sw[0];
  #pragma unroll
  for(int i=1;i<8;i++) M=fmaxf(M,sw[i]);
  float acc=0.f;
  for(int i=t;i<16384;i+=256) acc+=expf(g_s[i]-M);
  acc=wredsum(acc);
  __syncthreads();
  if(lane==0) sw[w]=acc;
  __syncthreads();
  if(t==0){
    float S=0.f;
    #pragma unroll
    for(int i=0;i<8;i++) S+=sw[i];
    g_red[0]=M; g_red[1]=S;
  }
}

// ---- per-b head on the single selected row ----
__global__ __launch_bounds__(128)
void gnn_k3(const float* __restrict__ fc3_w, const float* __restrict__ fc3_b,
            const float* __restrict__ ln3_g, const float* __restrict__ ln3_b,
            const float* __restrict__ fc4_w, const float* __restrict__ fc4_b,
            const float* __restrict__ ln4_g, const float* __restrict__ ln4_b,
            const int* __restrict__ agent_id, float* __restrict__ out)
{
  __shared__ float shf[128], sy[128], sred[8];
  int b=blockIdx.x, t=threadIdx.x, lane=t&31, w=t>>5;
  shf[t]=g_hfsel[b*128+t];
  __syncthreads();
  float acc=fc3_b[t];
  #pragma unroll 4
  for(int k=0;k<128;k++) acc=fmaf(shf[k],fc3_w[k*128+t],acc);
  float v=fmaxf(acc,0.f);
  float s1=wredsum(v), s2=wredsum(v*v);
  if(lane==0){sred[w]=s1; sred[4+w]=s2;}
  __syncthreads();
  s1=sred[0]+sred[1]+sred[2]+sred[3];
  s2=sred[4]+sred[5]+sred[6]+sred[7];
  float mu=s1*(1.f/128.f);
  float inv=rsqrtf(s2*(1.f/128.f)-mu*mu+1e-5f);
  float vn=(v-mu)*inv*ln3_g[t]+ln3_b[t];
  int ag=agent_id[b];
  float alpha=expf(g_s[b*32+ag]-g_red[0])/g_red[1];
  sy[t]=alpha*vn;
  __syncthreads();
  acc=fc4_b[t];
  #pragma unroll 4
  for(int k=0;k<128;k++) acc=fmaf(sy[k],fc4_w[k*128+t],acc);
  v=fmaxf(acc,0.f);
  s1=wredsum(v); s2=wredsum(v*v);
  __syncthreads();
  if(lane==0){sred[w]=s1; sred[4+w]=s2;}
  __syncthreads();
  s1=sred[0]+sred[1]+sred[2]+sred[3];
  s2=sred[4]+sred[5]+sred[6]+sred[7];
  mu=s1*(1.f/128.f);
  inv=rsqrtf(s2*(1.f/128.f)-mu*mu+1e-5f);
  out[b*128+t]=(v-mu)*inv*ln4_g[t]+ln4_b[t];
}

extern "C" void kernel_launch(void* const* d_in, const int* in_sizes, int n_in,
                              void* d_out, int out_size)
{
  const float* node_obs=(const float*)d_in[0];
  const float* adj     =(const float*)d_in[1];
  const int*   agent_id=(const int*)  d_in[2];
  const float* emb     =(const float*)d_in[3];
  const float* lin1_w  =(const float*)d_in[4];
  const float* lin1_b  =(const float*)d_in[5];
  const float* ln1_g   =(const float*)d_in[6];
  const float* ln1_b   =(const float*)d_in[7];
  const float* linh_w  =(const float*)d_in[8];
  const float* linh_b  =(const float*)d_in[9];
  const float* lnh_g   =(const float*)d_in[10];
  const float* lnh_b   =(const float*)d_in[11];
  const float* fc2a_w  =(const float*)d_in[12];
  const float* fc2a_b  =(const float*)d_in[13];
  const float* fc2b_w  =(const float*)d_in[14];
  const float* fc2b_b  =(const float*)d_in[15];
  const float* fc3_w   =(const float*)d_in[16];
  const float* fc3_b   =(const float*)d_in[17];
  const float* ln3_g   =(const float*)d_in[18];
  const float* ln3_b   =(const float*)d_in[19];
  const float* fc4_w   =(const float*)d_in[20];
  const float* fc4_b   =(const float*)d_in[21];
  const float* ln4_g   =(const float*)d_in[22];
  const float* ln4_b   =(const float*)d_in[23];

  cudaFuncSetAttribute(gnn_k1, cudaFuncAttributeMaxDynamicSharedMemorySize, SMEM_BYTES);

  gnn_k1<<<512,512,SMEM_BYTES>>>(node_obs,adj,agent_id,emb,
                                 lin1_w,lin1_b,ln1_g,ln1_b,
                                 linh_w,linh_b,lnh_g,lnh_b,
                                 fc2a_w,fc2a_b,fc2b_w,fc2b_b);
  gnn_k2<<<1,256>>>();
  gnn_k3<<<512,128>>>(fc3_w,fc3_b,ln3_g,ln3_b,fc4_w,fc4_b,ln4_g,ln4_b,
                      agent_id,(float*)d_out);
}

// round 14
// speedup vs baseline: 1.5710x; 1.5710x over previous
#include <cuda_runtime.h>
#include <cuda_bf16.h>

#define FULLMASK 0xffffffffu

// scratch (allocation-free contract: __device__ globals)
__device__ float g_s[16384];        // softmax logits, one per (b, c)
__device__ float g_hfsel[512*128];  // hf row at agent_id per b
__device__ float g_red[2];          // softmax max, sumexp

__device__ __forceinline__ float wredsum(float v){
  #pragma unroll
  for(int o=16;o;o>>=1) v += __shfl_xor_sync(FULLMASK,v,o);
  return v;
}

// ---- warp-level bf16 MMA (baseline PTX, sm_80+; runs on tensor pipe) ----
__device__ __forceinline__ void mma16816(float* d, const unsigned* a, unsigned b0, unsigned b1){
  asm volatile("mma.sync.aligned.m16n8k16.row.col.f32.bf16.bf16.f32 "
    "{%0,%1,%2,%3}, {%4,%5,%6,%7}, {%8,%9}, {%0,%1,%2,%3};"
    : "+f"(d[0]),"+f"(d[1]),"+f"(d[2]),"+f"(d[3])
    : "r"(a[0]),"r"(a[1]),"r"(a[2]),"r"(a[3]), "r"(b0),"r"(b1));
}

// split x = hi + lo (both bf16), pack adjacent pairs (even elem low half)
__device__ __forceinline__ void splitpair(float a, float b, unsigned &hi, unsigned &lo){
  __nv_bfloat16 ha=__float2bfloat16_rn(a), hb=__float2bfloat16_rn(b);
  __nv_bfloat16 la=__float2bfloat16_rn(a-__bfloat162float(ha));
  __nv_bfloat16 lb=__float2bfloat16_rn(b-__bfloat162float(hb));
  hi=(unsigned)__bfloat16_as_ushort(ha)|((unsigned)__bfloat16_as_ushort(hb)<<16);
  lo=(unsigned)__bfloat16_as_ushort(la)|((unsigned)__bfloat16_as_ushort(lb)<<16);
}

// ---- smem byte layout ----
// W rows [n][k] bf16, stride 136 elems (272B) -> conflict-free frag loads
#define B_WH2 0        // 34816  layer2 W hi
#define B_WL2 34816    // 34816  layer2 W lo
#define B_WH3 69632    // 34816  layer3 W hi
#define B_WL3 104448   // 34816  layer3 W lo
#define B_AH  139264   // 34816  act hi [e][k] (also: compaction scratch, final hacc)
#define B_AL  174080   // 34816  act lo       (also: xj preamble)
#define B_BASE 208896  // 16896  base[r][h] fp32 stride 132 (stage B: biases)
#define B_EL  225792   // 3072   e values (768 floats)
#define B_CL  228864   // 1536   (c<<5)|r shorts (768)
#define B_P1  230400   // 1536   w1row[128], ln1g[128], ln1b[128]
#define SMEM_BYTES 231936

__global__ __launch_bounds__(256,1)
void gnn_k1(const float* __restrict__ node_obs, const float* __restrict__ adj,
            const int* __restrict__ agent_id, const float* __restrict__ emb,
            const float* __restrict__ lin1_w, const float* __restrict__ lin1_b,
            const float* __restrict__ ln1_g, const float* __restrict__ ln1_b,
            const float* __restrict__ linh_w, const float* __restrict__ linh_b,
            const float* __restrict__ lnh_g, const float* __restrict__ lnh_b,
            const float* __restrict__ fc2a_w, const float* __restrict__ fc2a_b,
            const float* __restrict__ fc2b_w, const float* __restrict__ fc2b_b)
{
  extern __shared__ __align__(16) char smc[];
  const int b=blockIdx.x, t=threadIdx.x, lane=t&31, w=t>>5;

  int*   scount=(int*)(smc+B_AH);     // scratch aliases act_hi (pre-tile only)
  int*   sstart=scount+32;            // 33 entries
  short* clist=(short*)(smc+B_CL);
  float* elist=(float*)(smc+B_EL);
  float* sxj  =(float*)(smc+B_AL);    // alias, preamble only
  float* sbase=(float*)(smc+B_BASE);
  float* p1   =(float*)(smc+B_P1);

  // ---- weights fp32 -> split bf16 hi/lo, [n][k] stride 136 ----
  {
    const float4* src=(const float4*)linh_w;   // [l][k][n]
    for(int i=t;i<8192;i+=256){
      int l=i>>12, rem=i&4095, k=rem>>5, n0=(rem&31)*4;
      float4 v=src[i];
      char* dh=smc+(l?B_WH3:B_WH2);
      char* dl=smc+(l?B_WL3:B_WL2);
      float vv[4]={v.x,v.y,v.z,v.w};
      #pragma unroll
      for(int j=0;j<4;j++){
        unsigned off=(unsigned)(((n0+j)*136+k)*2);
        __nv_bfloat16 h=__float2bfloat16_rn(vv[j]);
        __nv_bfloat16 lo=__float2bfloat16_rn(vv[j]-__bfloat162float(h));
        *(__nv_bfloat16*)(dh+off)=h; *(__nv_bfloat16*)(dl+off)=lo;
      }
    }
  }
  if(t<128){ p1[t]=lin1_w[31*128+t]; p1[128+t]=ln1_g[t]; p1[256+t]=ln1_b[t]; }
  if(t<32){
    const int r=t;
    const float* no=node_obs+(size_t)b*512+r*16;
    #pragma unroll
    for(int k=0;k<15;k++) sxj[r*32+k]=no[k];
    int ent=(int)no[15];
    #pragma unroll
    for(int j=0;j<16;j++) sxj[r*32+15+j]=emb[ent*16+j];
    sxj[r*32+31]=0.f;
  }
  if(t<32) scount[t]=0;
  for(int i=t;i<768;i+=256){ clist[i]=-1; elist[i]=0.f; }
  __syncthreads();

  // ---- base[r][h] = xj[r] @ W1[0:31] + b1 (fp32, stride 132) ----
  {
    const int h=t&127, r0=t>>7;
    float acc[16];
    float bv=lin1_b[h];
    #pragma unroll
    for(int j=0;j<16;j++) acc[j]=bv;
    for(int k=0;k<31;k++){
      float wv=lin1_w[k*128+h];
      #pragma unroll
      for(int j=0;j<16;j++) acc[j]=fmaf(sxj[(r0+2*j)*32+k],wv,acc[j]);
    }
    #pragma unroll
    for(int j=0;j<16;j++) sbase[(r0+2*j)*132+h]=acc[j];
  }

  // ---- edge compaction (c-major): 4 edges/thread, c = t>>3 ----
  int nact;
  {
    const float* padj=adj+(size_t)b*1024;
    const int cc=t>>3;
    float ev[4]; int rv[4], av[4]; int cnt=0;
    #pragma unroll
    for(int q=0;q<4;q++){
      int idx=t*4+q, r=idx&31;
      float v=padj[r*32+cc];
      int a=(v>0.f)&&(v<1.0f);
      av[q]=a; ev[q]=v; rv[q]=r; cnt+=a;
    }
    if(cnt) atomicAdd(&scount[cc],cnt);
    int x=cnt;
    #pragma unroll
    for(int o=1;o<32;o<<=1){ int y=__shfl_up_sync(FULLMASK,x,o); if(lane>=o)x+=y; }
    __syncthreads();
    if(t==0){ int run=0;
      #pragma unroll
      for(int c=0;c<32;c++){ sstart[c]=run; run+=scount[c]; }
      sstart[32]=run;
    }
    __syncthreads();
    nact=sstart[32]; if(nact>768)nact=768;
    int pos=sstart[w*4]+x-cnt;
    #pragma unroll
    for(int q=0;q<4;q++){
      if(av[q]&&pos<768){ clist[pos]=(short)((cc<<5)|rv[q]); elist[pos]=ev[q]; pos++; }
    }
    __syncthreads();   // scratch (act area) now dead -> tiles may write act
  }

  const char* actH=smc+B_AH;
  const char* actL=smc+B_AL;
  const int cb=(w&1)*16+(lane>>2);   // agg-mma c row
  const int nt0=(w>>1)*4;            // agg-mma ntile group
  const int col0=(lane&3)*2;

  float hD[4][4];
  #pragma unroll
  for(int j=0;j<4;j++){hD[j][0]=0;hD[j][1]=0;hD[j][2]=0;hD[j][3]=0;}

  const int ntiles=(nact+127)>>7;
  for(int T=0;T<ntiles;T++){
    const int tb=T<<7;
    // ===== layer 1: 2 threads per edge (k halves), LN, split -> act =====
    {
      const int el=16*w+(lane>>1);       // warp-local edges match its m-tile
      const int khalf=lane&1;
      const int gi=tb+el;
      short cv=clist[gi];
      int r=cv&31; float e=elist[gi];
      const float4* brow=(const float4*)(sbase+r*132+khalf*64);
      const float4* w14=(const float4*)(p1+khalf*64);
      const float4* g14=(const float4*)(p1+128+khalf*64);
      const float4* b14=(const float4*)(p1+256+khalf*64);
      float s=0.f,p=0.f;
      #pragma unroll
      for(int q=0;q<16;q++){
        float4 bs=brow[q], wv=w14[q];
        float v0=fmaxf(fmaf(e,wv.x,bs.x),0.f);
        float v1=fmaxf(fmaf(e,wv.y,bs.y),0.f);
        float v2=fmaxf(fmaf(e,wv.z,bs.z),0.f);
        float v3=fmaxf(fmaf(e,wv.w,bs.w),0.f);
        s+=v0+v1+v2+v3;
        p=fmaf(v0,v0,fmaf(v1,v1,fmaf(v2,v2,fmaf(v3,v3,p))));
      }
      s+=__shfl_xor_sync(FULLMASK,s,1);
      p+=__shfl_xor_sync(FULLMASK,p,1);
      float mu=s*(1.f/128.f);
      float inv=rsqrtf(p*(1.f/128.f)-mu*mu+1e-5f);
      char* dh=(char*)actH+(el*136+khalf*64)*2;
      char* dl=(char*)actL+(el*136+khalf*64)*2;
      #pragma unroll
      for(int q=0;q<16;q++){
        float4 bs=brow[q], wv=w14[q], g=g14[q], bb=b14[q];
        float o0=(fmaxf(fmaf(e,wv.x,bs.x),0.f)-mu)*inv*g.x+bb.x;
        float o1=(fmaxf(fmaf(e,wv.y,bs.y),0.f)-mu)*inv*g.y+bb.y;
        float o2=(fmaxf(fmaf(e,wv.z,bs.z),0.f)-mu)*inv*g.z+bb.z;
        float o3=(fmaxf(fmaf(e,wv.w,bs.w),0.f)-mu)*inv*g.w+bb.w;
        unsigned h0,l0,h1,l1;
        splitpair(o0,o1,h0,l0); splitpair(o2,o3,h1,l1);
        *(uint2*)(dh+q*8)=make_uint2(h0,h1);
        *(uint2*)(dl+q*8)=make_uint2(l0,l1);
      }
    }

    // ===== two hidden layers: warp-local 16x128x128 split-bf16 MMA =====
    #pragma unroll 1
    for(int l=0;l<2;l++){
      __syncwarp();
      const char* ahp=actH+((16*w+(lane>>2))*136+col0)*2;
      const char* alp=actL+((16*w+(lane>>2))*136+col0)*2;
      unsigned Ah[8][4], Al[8][4];
      #pragma unroll
      for(int kk=0;kk<8;kk++){
        const char* pa=ahp+kk*32;
        Ah[kk][0]=*(const unsigned*)(pa);
        Ah[kk][1]=*(const unsigned*)(pa+2176);
        Ah[kk][2]=*(const unsigned*)(pa+16);
        Ah[kk][3]=*(const unsigned*)(pa+2192);
        const char* pl=alp+kk*32;
        Al[kk][0]=*(const unsigned*)(pl);
        Al[kk][1]=*(const unsigned*)(pl+2176);
        Al[kk][2]=*(const unsigned*)(pl+16);
        Al[kk][3]=*(const unsigned*)(pl+2192);
      }
      float d[16][4];
      #pragma unroll
      for(int n=0;n<16;n++){d[n][0]=0;d[n][1]=0;d[n][2]=0;d[n][3]=0;}
      const char* whp=smc+(l?B_WH3:B_WH2)+((lane>>2)*136+col0)*2;
      const char* wlp=smc+(l?B_WL3:B_WL2)+((lane>>2)*136+col0)*2;
      #pragma unroll 1
      for(int kk=0;kk<8;kk++){
        const char* ph=whp+kk*32;
        const char* pq=wlp+kk*32;
        #pragma unroll
        for(int n=0;n<16;n++){
          unsigned bh0=*(const unsigned*)(ph+n*2176);
          unsigned bh1=*(const unsigned*)(ph+n*2176+16);
          unsigned bl0=*(const unsigned*)(pq+n*2176);
          unsigned bl1=*(const unsigned*)(pq+n*2176+16);
          mma16816(d[n],Ah[kk],bh0,bh1);
          mma16816(d[n],Al[kk],bh0,bh1);
          mma16816(d[n],Ah[kk],bl0,bl1);
        }
      }
      // epilogue: bias+relu+LN (rows r0=16w+(lane>>2), r1=r0+8), split -> act
      const float* lhbg=linh_b+l*128;
      float2 bias[16];
      #pragma unroll
      for(int n=0;n<16;n++) bias[n]=*(const float2*)(lhbg+n*8+col0);
      float s0=0,p0=0,s1=0,q1=0;
      #pragma unroll
      for(int n=0;n<16;n++){
        float v0=fmaxf(d[n][0]+bias[n].x,0.f);
        float v1=fmaxf(d[n][1]+bias[n].y,0.f);
        float v2=fmaxf(d[n][2]+bias[n].x,0.f);
        float v3=fmaxf(d[n][3]+bias[n].y,0.f);
        s0+=v0+v1; p0=fmaf(v0,v0,fmaf(v1,v1,p0));
        s1+=v2+v3; q1=fmaf(v2,v2,fmaf(v3,v3,q1));
      }
      #pragma unroll
      for(int o=1;o<4;o<<=1){
        s0+=__shfl_xor_sync(FULLMASK,s0,o);
        p0+=__shfl_xor_sync(FULLMASK,p0,o);
        s1+=__shfl_xor_sync(FULLMASK,s1,o);
        q1+=__shfl_xor_sync(FULLMASK,q1,o);
      }
      float mu0=s0*(1.f/128.f), inv0=rsqrtf(p0*(1.f/128.f)-mu0*mu0+1e-5f);
      float mu1=s1*(1.f/128.f), inv1=rsqrtf(q1*(1.f/128.f)-mu1*mu1+1e-5f);
      const float* gg=lnh_g+l*128;
      const float* b2g=lnh_b+l*128;
      char* sh0=(char*)actH+((16*w+(lane>>2))*136+col0)*2;
      char* sl0=(char*)actL+((16*w+(lane>>2))*136+col0)*2;
      #pragma unroll
      for(int n=0;n<16;n++){
        float2 g=*(const float2*)(gg+n*8+col0);
        float2 b2=*(const float2*)(b2g+n*8+col0);
        float o0=(fmaxf(d[n][0]+bias[n].x,0.f)-mu0)*inv0*g.x+b2.x;
        float o1=(fmaxf(d[n][1]+bias[n].y,0.f)-mu0)*inv0*g.y+b2.y;
        float o2=(fmaxf(d[n][2]+bias[n].x,0.f)-mu1)*inv1*g.x+b2.x;
        float o3=(fmaxf(d[n][3]+bias[n].y,0.f)-mu1)*inv1*g.y+b2.y;
        unsigned h0,l0,h1,l1;
        splitpair(o0,o1,h0,l0); splitpair(o2,o3,h1,l1);
        *(unsigned*)(sh0+n*16)=h0;
        *(unsigned*)(sh0+n*16+2176)=h1;
        *(unsigned*)(sl0+n*16)=l0;
        *(unsigned*)(sl0+n*16+2176)=l1;
      }
    }

    // ===== aggregation: h += sel(c,e) @ m via MMA (sel exact 0/1) =====
    // el0 = TILE-LOCAL edge index (act arrays hold 128 edges); e0 = global (clist)
    __syncthreads();
    #pragma unroll 1
    for(int kk=0;kk<8;kk++){
      int el0=kk*16+col0;
      int e0=tb+el0;
      int c0v=clist[e0]>>5, c1v=clist[e0+1]>>5;
      int c2v=clist[e0+8]>>5, c3v=clist[e0+9]>>5;
      unsigned A[4];
      A[0]=(c0v==cb  ?0x3F80u:0u)|((c1v==cb  )?0x3F800000u:0u);
      A[1]=(c0v==cb+8?0x3F80u:0u)|((c1v==cb+8)?0x3F800000u:0u);
      A[2]=(c2v==cb  ?0x3F80u:0u)|((c3v==cb  )?0x3F800000u:0u);
      A[3]=(c2v==cb+8?0x3F80u:0u)|((c3v==cb+8)?0x3F800000u:0u);
      #pragma unroll
      for(int j=0;j<4;j++){
        int nn=(nt0+j)*8+(lane>>2);
        unsigned x0,x1,bh0,bh1,bl0,bl1;
        x0=*(const unsigned short*)(actH+(el0*136+nn)*2);
        x1=*(const unsigned short*)(actH+((el0+1)*136+nn)*2);
        bh0=x0|(x1<<16);
        x0=*(const unsigned short*)(actH+((el0+8)*136+nn)*2);
        x1=*(const unsigned short*)(actH+((el0+9)*136+nn)*2);
        bh1=x0|(x1<<16);
        x0=*(const unsigned short*)(actL+(el0*136+nn)*2);
        x1=*(const unsigned short*)(actL+((el0+1)*136+nn)*2);
        bl0=x0|(x1<<16);
        x0=*(const unsigned short*)(actL+((el0+8)*136+nn)*2);
        x1=*(const unsigned short*)(actL+((el0+9)*136+nn)*2);
        bl1=x0|(x1<<16);
        mma16816(hD[j],A,bh0,bh1);
        mma16816(hD[j],A,bl0,bl1);
      }
    }
    __syncthreads();   // agg reads done before next tile's layer-1 writes
  }

  // ---- write h to smem (act region dead) ----
  float* hacc=(float*)(smc+B_AH);
  __syncthreads();
  #pragma unroll
  for(int j=0;j<4;j++){
    int col=(nt0+j)*8+col0;
    hacc[cb*132+col]  =hD[j][0];
    hacc[cb*132+col+1]=hD[j][1];
    hacc[(cb+8)*132+col]  =hD[j][2];
    hacc[(cb+8)*132+col+1]=hD[j][3];
  }
  __syncthreads();

  // ---- stage B: s[b,c] = relu(h @ fc2a + b2a) @ fc2b + b2b ----
  float* w2s=(float*)(smc+B_WH2);
  {
    const float4* s2=(const float4*)fc2a_w; float4* d2=(float4*)w2s;
    for(int i=t;i<4096;i+=256) d2[i]=s2[i];
    float* bb=(float*)(smc+B_BASE);
    if(t<128){ bb[t]=fc2a_b[t]; bb[128+t]=fc2b_w[t]; }
  }
  __syncthreads();
  {
    const float* bb=(const float*)(smc+B_BASE);
    float4 b2=((const float4*)bb)[lane];
    float4 f2=((const float4*)(bb+128))[lane];
    float acc[4][4];
    #pragma unroll
    for(int cc=0;cc<4;cc++){acc[cc][0]=b2.x;acc[cc][1]=b2.y;acc[cc][2]=b2.z;acc[cc][3]=b2.w;}
    const int c0=w*4;
    #pragma unroll 4
    for(int k=0;k<128;k++){
      float4 wv=((const float4*)w2s)[k*32+lane];
      #pragma unroll
      for(int cc=0;cc<4;cc++){
        float a=hacc[(c0+cc)*132+k];
        acc[cc][0]=fmaf(a,wv.x,acc[cc][0]);
        acc[cc][1]=fmaf(a,wv.y,acc[cc][1]);
        acc[cc][2]=fmaf(a,wv.z,acc[cc][2]);
        acc[cc][3]=fmaf(a,wv.w,acc[cc][3]);
      }
    }
    float b2b=fc2b_b[0];
    #pragma unroll
    for(int cc=0;cc<4;cc++){
      float p=fmaxf(acc[cc][0],0.f)*f2.x+fmaxf(acc[cc][1],0.f)*f2.y
             +fmaxf(acc[cc][2],0.f)*f2.z+fmaxf(acc[cc][3],0.f)*f2.w;
      p=wredsum(p);
      if(lane==0) g_s[b*32+c0+cc]=p+b2b;
    }
  }
  if(t<128){
    int ag=agent_id[b];
    g_hfsel[b*128+t]=hacc[ag*132+t];
  }
}

// ---- global softmax reduction over 16384 logits ----
__global__ void gnn_k2(){
  __shared__ float sw[8];
  int t=threadIdx.x, lane=t&31, w=t>>5;
  float m=-3.4e38f;
  for(int i=t;i<16384;i+=256) m=fmaxf(m,g_s[i]);
  #pragma unroll
  for(int o=16;o;o>>=1) m=fmaxf(m,__shfl_xor_sync(FULLMASK,m,o));
  if(lane==0) sw[w]=m;
  __syncthreads();
  float M=sw[0];
  #pragma unroll
  for(int i=1;i<8;i++) M=fmaxf(M,sw[i]);
  float acc=0.f;
  for(int i=t;i<16384;i+=256) acc+=expf(g_s[i]-M);
  acc=wredsum(acc);
  __syncthreads();
  if(lane==0) sw[w]=acc;
  __syncthreads();
  if(t==0){
    float S=0.f;
    #pragma unroll
    for(int i=0;i<8;i++) S+=sw[i];
    g_red[0]=M; g_red[1]=S;
  }
}

// ---- per-b head on the single selected row ----
__global__ __launch_bounds__(128)
void gnn_k3(const float* __restrict__ fc3_w, const float* __restrict__ fc3_b,
            const float* __restrict__ ln3_g, const float* __restrict__ ln3_b,
            const float* __restrict__ fc4_w, const float* __restrict__ fc4_b,
            const float* __restrict__ ln4_g, const float* __restrict__ ln4_b,
            const int* __restrict__ agent_id, float* __restrict__ out)
{
  __shared__ float shf[128], sy[128], sred[8];
  int b=blockIdx.x, t=threadIdx.x, lane=t&31, w=t>>5;
  shf[t]=g_hfsel[b*128+t];
  __syncthreads();
  float acc=fc3_b[t];
  #pragma unroll 4
  for(int k=0;k<128;k++) acc=fmaf(shf[k],fc3_w[k*128+t],acc);
  float v=fmaxf(acc,0.f);
  float s1=wredsum(v), s2=wredsum(v*v);
  if(lane==0){sred[w]=s1; sred[4+w]=s2;}
  __syncthreads();
  s1=sred[0]+sred[1]+sred[2]+sred[3];
  s2=sred[4]+sred[5]+sred[6]+sred[7];
  float mu=s1*(1.f/128.f);
  float inv=rsqrtf(s2*(1.f/128.f)-mu*mu+1e-5f);
  float vn=(v-mu)*inv*ln3_g[t]+ln3_b[t];
  int ag=agent_id[b];
  float alpha=expf(g_s[b*32+ag]-g_red[0])/g_red[1];
  sy[t]=alpha*vn;
  __syncthreads();
  acc=fc4_b[t];
  #pragma unroll 4
  for(int k=0;k<128;k++) acc=fmaf(sy[k],fc4_w[k*128+t],acc);
  v=fmaxf(acc,0.f);
  s1=wredsum(v); s2=wredsum(v*v);
  __syncthreads();
  if(lane==0){sred[w]=s1; sred[4+w]=s2;}
  __syncthreads();
  s1=sred[0]+sred[1]+sred[2]+sred[3];
  s2=sred[4]+sred[5]+sred[6]+sred[7];
  mu=s1*(1.f/128.f);
  inv=rsqrtf(s2*(1.f/128.f)-mu*mu+1e-5f);
  out[b*128+t]=(v-mu)*inv*ln4_g[t]+ln4_b[t];
}

extern "C" void kernel_launch(void* const* d_in, const int* in_sizes, int n_in,
                              void* d_out, int out_size)
{
  const float* node_obs=(const float*)d_in[0];
  const float* adj     =(const float*)d_in[1];
  const int*   agent_id=(const int*)  d_in[2];
  const float* emb     =(const float*)d_in[3];
  const float* lin1_w  =(const float*)d_in[4];
  const float* lin1_b  =(const float*)d_in[5];
  const float* ln1_g   =(const float*)d_in[6];
  const float* ln1_b   =(const float*)d_in[7];
  const float* linh_w  =(const float*)d_in[8];
  const float* linh_b  =(const float*)d_in[9];
  const float* lnh_g   =(const float*)d_in[10];
  const float* lnh_b   =(const float*)d_in[11];
  const float* fc2a_w  =(const float*)d_in[12];
  const float* fc2a_b  =(const float*)d_in[13];
  const float* fc2b_w  =(const float*)d_in[14];
  const float* fc2b_b  =(const float*)d_in[15];
  const float* fc3_w   =(const float*)d_in[16];
  const float* fc3_b   =(const float*)d_in[17];
  const float* ln3_g   =(const float*)d_in[18];
  const float* ln3_b   =(const float*)d_in[19];
  const float* fc4_w   =(const float*)d_in[20];
  const float* fc4_b   =(const float*)d_in[21];
  const float* ln4_g   =(const float*)d_in[22];
  const float* ln4_b   =(const float*)d_in[23];

  cudaFuncSetAttribute(gnn_k1, cudaFuncAttributeMaxDynamicSharedMemorySize, SMEM_BYTES);

  gnn_k1<<<512,256,SMEM_BYTES>>>(node_obs,adj,agent_id,emb,
                                 lin1_w,lin1_b,ln1_g,ln1_b,
                                 linh_w,linh_b,lnh_g,lnh_b,
                                 fc2a_w,fc2a_b,fc2b_w,fc2b_b);
  gnn_k2<<<1,256>>>();
  gnn_k3<<<512,128>>>(fc3_w,fc3_b,ln3_g,ln3_b,fc4_w,fc4_b,ln4_g,ln4_b,
                      agent_id,(float*)d_out);
}

// round 15
// speedup vs baseline: 1.6356x; 1.0412x over previous
#include <cuda_runtime.h>
#include <cuda_bf16.h>

#define FULLMASK 0xffffffffu

// scratch (allocation-free contract: __device__ globals)
__device__ float g_s[16384];        // softmax logits, one per (b, c)
__device__ float g_hfsel[512*128];  // hf row at agent_id per b
__device__ float g_red[2];          // softmax max, sumexp

__device__ __forceinline__ float wredsum(float v){
  #pragma unroll
  for(int o=16;o;o>>=1) v += __shfl_xor_sync(FULLMASK,v,o);
  return v;
}

__device__ __forceinline__ unsigned smem_u32(const void* p){
  unsigned a;
  asm("{ .reg .u64 t; cvta.to.shared.u64 t, %1; cvt.u32.u64 %0, t; }" : "=r"(a) : "l"(p));
  return a;
}

// ---- warp-level bf16 MMA (baseline PTX, sm_80+; runs on tensor pipe) ----
__device__ __forceinline__ void mma16816(float* d, const unsigned* a, unsigned b0, unsigned b1){
  asm volatile("mma.sync.aligned.m16n8k16.row.col.f32.bf16.bf16.f32 "
    "{%0,%1,%2,%3}, {%4,%5,%6,%7}, {%8,%9}, {%0,%1,%2,%3};"
    : "+f"(d[0]),"+f"(d[1]),"+f"(d[2]),"+f"(d[3])
    : "r"(a[0]),"r"(a[1]),"r"(a[2]),"r"(a[3]), "r"(b0),"r"(b1));
}

// ---- ldmatrix/stmatrix (baseline PTX sm_75+/sm_90+) ----
__device__ __forceinline__ void ldsm4(unsigned* r, unsigned a){
  asm volatile("ldmatrix.sync.aligned.m8n8.x4.shared.b16 {%0,%1,%2,%3}, [%4];"
    : "=r"(r[0]),"=r"(r[1]),"=r"(r[2]),"=r"(r[3]) : "r"(a));
}
__device__ __forceinline__ void ldsm4t(unsigned* r, unsigned a){
  asm volatile("ldmatrix.sync.aligned.m8n8.x4.trans.shared.b16 {%0,%1,%2,%3}, [%4];"
    : "=r"(r[0]),"=r"(r[1]),"=r"(r[2]),"=r"(r[3]) : "r"(a));
}
__device__ __forceinline__ void stsm2(unsigned a, unsigned r0, unsigned r1){
  asm volatile("stmatrix.sync.aligned.m8n8.x2.shared.b16 [%0], {%1,%2};"
    :: "r"(a),"r"(r0),"r"(r1) : "memory");
}

// split x = hi + lo (both bf16), pack adjacent pairs (even elem low half)
__device__ __forceinline__ void splitpair(float a, float b, unsigned &hi, unsigned &lo){
  __nv_bfloat16 ha=__float2bfloat16_rn(a), hb=__float2bfloat16_rn(b);
  __nv_bfloat16 la=__float2bfloat16_rn(a-__bfloat162float(ha));
  __nv_bfloat16 lb=__float2bfloat16_rn(b-__bfloat162float(hb));
  hi=(unsigned)__bfloat16_as_ushort(ha)|((unsigned)__bfloat16_as_ushort(hb)<<16);
  lo=(unsigned)__bfloat16_as_ushort(la)|((unsigned)__bfloat16_as_ushort(lb)<<16);
}

// ---- smem byte layout ----
// W rows [n][k] bf16, stride 136 elems (272B) -> conflict-free frag loads
#define B_WH2 0        // 34816  layer2 W hi
#define B_WL2 34816    // 34816  layer2 W lo
#define B_WH3 69632    // 34816  layer3 W hi
#define B_WL3 104448   // 34816  layer3 W lo
#define B_AH  139264   // 34816  act hi [e][k] (also: compaction scratch, final hacc)
#define B_AL  174080   // 34816  act lo       (also: xj preamble)
#define B_BASE 208896  // 16896  base[r][h] fp32 stride 132 (stage B: biases)
#define B_EL  225792   // 3072   e values (768 floats)
#define B_CL  228864   // 1536   (c<<5)|r shorts (768)
#define B_P1  230400   // 1536   w1row[128], ln1g[128], ln1b[128]
#define SMEM_BYTES 231936

__global__ __launch_bounds__(256,1)
void gnn_k1(const float* __restrict__ node_obs, const float* __restrict__ adj,
            const int* __restrict__ agent_id, const float* __restrict__ emb,
            const float* __restrict__ lin1_w, const float* __restrict__ lin1_b,
            const float* __restrict__ ln1_g, const float* __restrict__ ln1_b,
            const float* __restrict__ linh_w, const float* __restrict__ linh_b,
            const float* __restrict__ lnh_g, const float* __restrict__ lnh_b,
            const float* __restrict__ fc2a_w, const float* __restrict__ fc2a_b,
            const float* __restrict__ fc2b_w, const float* __restrict__ fc2b_b)
{
  extern __shared__ __align__(16) char smc[];
  const int b=blockIdx.x, t=threadIdx.x, lane=t&31, w=t>>5;
  const unsigned sbase = smem_u32(smc);

  int*   scount=(int*)(smc+B_AH);     // scratch aliases act_hi (pre-tile only)
  int*   sstart=scount+32;            // 33 entries
  short* clist=(short*)(smc+B_CL);
  float* elist=(float*)(smc+B_EL);
  float* sxj  =(float*)(smc+B_AL);    // alias, preamble only
  float* sbase_f=(float*)(smc+B_BASE);
  float* p1   =(float*)(smc+B_P1);

  // ---- weights fp32 -> split bf16 hi/lo, [n][k] stride 136 ----
  {
    const float4* src=(const float4*)linh_w;   // [l][k][n]
    for(int i=t;i<8192;i+=256){
      int l=i>>12, rem=i&4095, k=rem>>5, n0=(rem&31)*4;
      float4 v=src[i];
      char* dh=smc+(l?B_WH3:B_WH2);
      char* dl=smc+(l?B_WL3:B_WL2);
      float vv[4]={v.x,v.y,v.z,v.w};
      #pragma unroll
      for(int j=0;j<4;j++){
        unsigned off=(unsigned)(((n0+j)*136+k)*2);
        __nv_bfloat16 h=__float2bfloat16_rn(vv[j]);
        __nv_bfloat16 lo=__float2bfloat16_rn(vv[j]-__bfloat162float(h));
        *(__nv_bfloat16*)(dh+off)=h; *(__nv_bfloat16*)(dl+off)=lo;
      }
    }
  }
  if(t<128){ p1[t]=lin1_w[31*128+t]; p1[128+t]=ln1_g[t]; p1[256+t]=ln1_b[t]; }
  if(t<32){
    const int r=t;
    const float* no=node_obs+(size_t)b*512+r*16;
    #pragma unroll
    for(int k=0;k<15;k++) sxj[r*32+k]=no[k];
    int ent=(int)no[15];
    #pragma unroll
    for(int j=0;j<16;j++) sxj[r*32+15+j]=emb[ent*16+j];
    sxj[r*32+31]=0.f;
  }
  if(t<32) scount[t]=0;
  for(int i=t;i<768;i+=256){ clist[i]=-1; elist[i]=0.f; }
  __syncthreads();

  // ---- base[r][h] = xj[r] @ W1[0:31] + b1 (fp32, stride 132) ----
  {
    const int h=t&127, r0=t>>7;
    float acc[16];
    float bv=lin1_b[h];
    #pragma unroll
    for(int j=0;j<16;j++) acc[j]=bv;
    for(int k=0;k<31;k++){
      float wv=lin1_w[k*128+h];
      #pragma unroll
      for(int j=0;j<16;j++) acc[j]=fmaf(sxj[(r0+2*j)*32+k],wv,acc[j]);
    }
    #pragma unroll
    for(int j=0;j<16;j++) sbase_f[(r0+2*j)*132+h]=acc[j];
  }

  // ---- edge compaction (c-major): 4 edges/thread, c = t>>3 ----
  int nact;
  {
    const float* padj=adj+(size_t)b*1024;
    const int cc=t>>3;
    float ev[4]; int rv[4], av[4]; int cnt=0;
    #pragma unroll
    for(int q=0;q<4;q++){
      int idx=t*4+q, r=idx&31;
      float v=padj[r*32+cc];
      int a=(v>0.f)&&(v<1.0f);
      av[q]=a; ev[q]=v; rv[q]=r; cnt+=a;
    }
    if(cnt) atomicAdd(&scount[cc],cnt);
    int x=cnt;
    #pragma unroll
    for(int o=1;o<32;o<<=1){ int y=__shfl_up_sync(FULLMASK,x,o); if(lane>=o)x+=y; }
    __syncthreads();
    if(t==0){ int run=0;
      #pragma unroll
      for(int c=0;c<32;c++){ sstart[c]=run; run+=scount[c]; }
      sstart[32]=run;
    }
    __syncthreads();
    nact=sstart[32]; if(nact>768)nact=768;
    int pos=sstart[w*4]+x-cnt;
    #pragma unroll
    for(int q=0;q<4;q++){
      if(av[q]&&pos<768){ clist[pos]=(short)((cc<<5)|rv[q]); elist[pos]=ev[q]; pos++; }
    }
    __syncthreads();   // scratch (act area) now dead -> tiles may write act
  }

  const char* actH=smc+B_AH;
  const char* actL=smc+B_AL;
  const unsigned actHu=sbase+B_AH, actLu=sbase+B_AL;
  const int cb=(w&1)*16+(lane>>2);   // agg-mma c row
  const int nt0=(w>>1)*4;            // agg-mma ntile group
  const int col0=(lane&3)*2;

  // ---- precomputed per-lane ldmatrix/stmatrix address offsets ----
  // GEMM A-frag: rows = edges 16w+(i&15), k chunk (i>>4)*8; + kk*32 bytes
  const unsigned aOffA = (unsigned)((16*w+(lane&15))*272 + (lane>>4)*16);
  // B-frag: rows = n (i&7) of n-tile, k chunk (i>>3)*8; + nt*2176 + kk2*64
  const unsigned bOff  = (unsigned)((lane&7)*272 + (lane>>3)*16);
  // stmatrix: rows = edges 16w+(i&15); + nt*16
  const unsigned sOff  = (unsigned)((16*w+(lane&15))*272);
  // agg trans-ldsm: rows = edges (i&15) of kk group, col base nt0*8 + (i>>4)*8
  const unsigned gOff  = (unsigned)((lane&15)*272 + (nt0*8 + (lane>>4)*8)*2);

  float hD[4][4];
  #pragma unroll
  for(int j=0;j<4;j++){hD[j][0]=0;hD[j][1]=0;hD[j][2]=0;hD[j][3]=0;}

  const int ntiles=(nact+127)>>7;
  for(int T=0;T<ntiles;T++){
    const int tb=T<<7;
    // ===== layer 1: 2 threads per edge (k halves), LN, split -> act =====
    {
      const int el=16*w+(lane>>1);       // warp-local edges match its m-tile
      const int khalf=lane&1;
      const int gi=tb+el;
      short cv=clist[gi];
      int r=cv&31; float e=elist[gi];
      const float4* brow=(const float4*)(sbase_f+r*132+khalf*64);
      const float4* w14=(const float4*)(p1+khalf*64);
      const float4* g14=(const float4*)(p1+128+khalf*64);
      const float4* b14=(const float4*)(p1+256+khalf*64);
      float s=0.f,p=0.f;
      #pragma unroll
      for(int q=0;q<16;q++){
        float4 bs=brow[q], wv=w14[q];
        float v0=fmaxf(fmaf(e,wv.x,bs.x),0.f);
        float v1=fmaxf(fmaf(e,wv.y,bs.y),0.f);
        float v2=fmaxf(fmaf(e,wv.z,bs.z),0.f);
        float v3=fmaxf(fmaf(e,wv.w,bs.w),0.f);
        s+=v0+v1+v2+v3;
        p=fmaf(v0,v0,fmaf(v1,v1,fmaf(v2,v2,fmaf(v3,v3,p))));
      }
      s+=__shfl_xor_sync(FULLMASK,s,1);
      p+=__shfl_xor_sync(FULLMASK,p,1);
      float mu=s*(1.f/128.f);
      float inv=rsqrtf(p*(1.f/128.f)-mu*mu+1e-5f);
      char* dh=(char*)actH+(el*136+khalf*64)*2;
      char* dl=(char*)actL+(el*136+khalf*64)*2;
      #pragma unroll
      for(int q=0;q<16;q++){
        float4 bs=brow[q], wv=w14[q], g=g14[q], bb=b14[q];
        float o0=(fmaxf(fmaf(e,wv.x,bs.x),0.f)-mu)*inv*g.x+bb.x;
        float o1=(fmaxf(fmaf(e,wv.y,bs.y),0.f)-mu)*inv*g.y+bb.y;
        float o2=(fmaxf(fmaf(e,wv.z,bs.z),0.f)-mu)*inv*g.z+bb.z;
        float o3=(fmaxf(fmaf(e,wv.w,bs.w),0.f)-mu)*inv*g.w+bb.w;
        unsigned h0,l0,h1,l1;
        splitpair(o0,o1,h0,l0); splitpair(o2,o3,h1,l1);
        *(uint2*)(dh+q*8)=make_uint2(h0,h1);
        *(uint2*)(dl+q*8)=make_uint2(l0,l1);
      }
    }

    // ===== two hidden layers: warp-local 16x128x128 split-bf16 MMA =====
    #pragma unroll 1
    for(int l=0;l<2;l++){
      __syncwarp();
      // A frags via ldmatrix.x4 (one per kk per hi/lo)
      unsigned Ah[8][4], Al[8][4];
      #pragma unroll
      for(int kk=0;kk<8;kk++){
        ldsm4(Ah[kk], actHu + aOffA + kk*32);
        ldsm4(Al[kk], actLu + aOffA + kk*32);
      }
      float d[16][4];
      #pragma unroll
      for(int n=0;n<16;n++){d[n][0]=0;d[n][1]=0;d[n][2]=0;d[n][3]=0;}
      const unsigned bBaseH = sbase + (l?B_WH3:B_WH2) + bOff;
      const unsigned bBaseL = sbase + (l?B_WL3:B_WL2) + bOff;
      #pragma unroll 1
      for(int kk2=0;kk2<4;kk2++){
        #pragma unroll
        for(int nt=0;nt<16;nt++){
          unsigned bh[4], bl[4];
          ldsm4(bh, bBaseH + nt*2176 + kk2*64);
          ldsm4(bl, bBaseL + nt*2176 + kk2*64);
          mma16816(d[nt],Ah[2*kk2],  bh[0],bh[1]);
          mma16816(d[nt],Al[2*kk2],  bh[0],bh[1]);
          mma16816(d[nt],Ah[2*kk2],  bl[0],bl[1]);
          mma16816(d[nt],Ah[2*kk2+1],bh[2],bh[3]);
          mma16816(d[nt],Al[2*kk2+1],bh[2],bh[3]);
          mma16816(d[nt],Ah[2*kk2+1],bl[2],bl[3]);
        }
      }
      // epilogue: bias+relu+LN (rows r0=16w+(lane>>2), r1=r0+8), split -> act
      const float* lhbg=linh_b+l*128;
      float2 bias[16];
      #pragma unroll
      for(int n=0;n<16;n++) bias[n]=*(const float2*)(lhbg+n*8+col0);
      float s0=0,p0=0,s1=0,q1=0;
      #pragma unroll
      for(int n=0;n<16;n++){
        float v0=fmaxf(d[n][0]+bias[n].x,0.f);
        float v1=fmaxf(d[n][1]+bias[n].y,0.f);
        float v2=fmaxf(d[n][2]+bias[n].x,0.f);
        float v3=fmaxf(d[n][3]+bias[n].y,0.f);
        s0+=v0+v1; p0=fmaf(v0,v0,fmaf(v1,v1,p0));
        s1+=v2+v3; q1=fmaf(v2,v2,fmaf(v3,v3,q1));
      }
      #pragma unroll
      for(int o=1;o<4;o<<=1){
        s0+=__shfl_xor_sync(FULLMASK,s0,o);
        p0+=__shfl_xor_sync(FULLMASK,p0,o);
        s1+=__shfl_xor_sync(FULLMASK,s1,o);
        q1+=__shfl_xor_sync(FULLMASK,q1,o);
      }
      float mu0=s0*(1.f/128.f), inv0=rsqrtf(p0*(1.f/128.f)-mu0*mu0+1e-5f);
      float mu1=s1*(1.f/128.f), inv1=rsqrtf(q1*(1.f/128.f)-mu1*mu1+1e-5f);
      const float* gg=lnh_g+l*128;
      const float* b2g=lnh_b+l*128;
      #pragma unroll
      for(int n=0;n<16;n++){
        float2 g=*(const float2*)(gg+n*8+col0);
        float2 b2=*(const float2*)(b2g+n*8+col0);
        float o0=(fmaxf(d[n][0]+bias[n].x,0.f)-mu0)*inv0*g.x+b2.x;
        float o1=(fmaxf(d[n][1]+bias[n].y,0.f)-mu0)*inv0*g.y+b2.y;
        float o2=(fmaxf(d[n][2]+bias[n].x,0.f)-mu1)*inv1*g.x+b2.x;
        float o3=(fmaxf(d[n][3]+bias[n].y,0.f)-mu1)*inv1*g.y+b2.y;
        unsigned h0,l0,h1,l1;
        splitpair(o0,o1,h0,l0); splitpair(o2,o3,h1,l1);
        stsm2(actHu + sOff + n*16, h0,h1);
        stsm2(actLu + sOff + n*16, l0,l1);
      }
    }

    // ===== aggregation: h += sel(c,e) @ m via MMA (sel exact 0/1) =====
    // act frags fetched column-wise via ldmatrix.trans (tile-local indices)
    __syncthreads();
    #pragma unroll 1
    for(int kk=0;kk<8;kk++){
      int e0=tb+kk*16+col0;   // global index into clist
      int c0v=clist[e0]>>5, c1v=clist[e0+1]>>5;
      int c2v=clist[e0+8]>>5, c3v=clist[e0+9]>>5;
      unsigned A[4];
      A[0]=(c0v==cb  ?0x3F80u:0u)|((c1v==cb  )?0x3F800000u:0u);
      A[1]=(c0v==cb+8?0x3F80u:0u)|((c1v==cb+8)?0x3F800000u:0u);
      A[2]=(c2v==cb  ?0x3F80u:0u)|((c3v==cb  )?0x3F800000u:0u);
      A[3]=(c2v==cb+8?0x3F80u:0u)|((c3v==cb+8)?0x3F800000u:0u);
      unsigned bhA[4],bhB[4],blA[4],blB[4];
      unsigned gh = actHu + gOff + kk*4352;
      unsigned gl2= actLu + gOff + kk*4352;
      ldsm4t(bhA, gh);     ldsm4t(bhB, gh+32);
      ldsm4t(blA, gl2);    ldsm4t(blB, gl2+32);
      mma16816(hD[0],A,bhA[0],bhA[1]); mma16816(hD[0],A,blA[0],blA[1]);
      mma16816(hD[1],A,bhA[2],bhA[3]); mma16816(hD[1],A,blA[2],blA[3]);
      mma16816(hD[2],A,bhB[0],bhB[1]); mma16816(hD[2],A,blB[0],blB[1]);
      mma16816(hD[3],A,bhB[2],bhB[3]); mma16816(hD[3],A,blB[2],blB[3]);
    }
    __syncthreads();   // agg reads done before next tile's layer-1 writes
  }

  // ---- write h to smem (act region dead) ----
  float* hacc=(float*)(smc+B_AH);
  __syncthreads();
  #pragma unroll
  for(int j=0;j<4;j++){
    int col=(nt0+j)*8+col0;
    hacc[cb*132+col]  =hD[j][0];
    hacc[cb*132+col+1]=hD[j][1];
    hacc[(cb+8)*132+col]  =hD[j][2];
    hacc[(cb+8)*132+col+1]=hD[j][3];
  }
  __syncthreads();

  // ---- stage B: s[b,c] = relu(h @ fc2a + b2a) @ fc2b + b2b ----
  float* w2s=(float*)(smc+B_WH2);
  {
    const float4* s2=(const float4*)fc2a_w; float4* d2=(float4*)w2s;
    for(int i=t;i<4096;i+=256) d2[i]=s2[i];
    float* bb=(float*)(smc+B_BASE);
    if(t<128){ bb[t]=fc2a_b[t]; bb[128+t]=fc2b_w[t]; }
  }
  __syncthreads();
  {
    const float* bb=(const float*)(smc+B_BASE);
    float4 b2=((const float4*)bb)[lane];
    float4 f2=((const float4*)(bb+128))[lane];
    float acc[4][4];
    #pragma unroll
    for(int cc=0;cc<4;cc++){acc[cc][0]=b2.x;acc[cc][1]=b2.y;acc[cc][2]=b2.z;acc[cc][3]=b2.w;}
    const int c0=w*4;
    #pragma unroll 4
    for(int k=0;k<128;k++){
      float4 wv=((const float4*)w2s)[k*32+lane];
      #pragma unroll
      for(int cc=0;cc<4;cc++){
        float a=hacc[(c0+cc)*132+k];
        acc[cc][0]=fmaf(a,wv.x,acc[cc][0]);
        acc[cc][1]=fmaf(a,wv.y,acc[cc][1]);
        acc[cc][2]=fmaf(a,wv.z,acc[cc][2]);
        acc[cc][3]=fmaf(a,wv.w,acc[cc][3]);
      }
    }
    float b2b=fc2b_b[0];
    #pragma unroll
    for(int cc=0;cc<4;cc++){
      float p=fmaxf(acc[cc][0],0.f)*f2.x+fmaxf(acc[cc][1],0.f)*f2.y
             +fmaxf(acc[cc][2],0.f)*f2.z+fmaxf(acc[cc][3],0.f)*f2.w;
      p=wredsum(p);
      if(lane==0) g_s[b*32+c0+cc]=p+b2b;
    }
  }
  if(t<128){
    int ag=agent_id[b];
    g_hfsel[b*128+t]=hacc[ag*132+t];
  }
}

// ---- global softmax reduction over 16384 logits ----
__global__ void gnn_k2(){
  __shared__ float sw[8];
  int t=threadIdx.x, lane=t&31, w=t>>5;
  float m=-3.4e38f;
  for(int i=t;i<16384;i+=256) m=fmaxf(m,g_s[i]);
  #pragma unroll
  for(int o=16;o;o>>=1) m=fmaxf(m,__shfl_xor_sync(FULLMASK,m,o));
  if(lane==0) sw[w]=m;
  __syncthreads();
  float M=sw[0];
  #pragma unroll
  for(int i=1;i<8;i++) M=fmaxf(M,sw[i]);
  float acc=0.f;
  for(int i=t;i<16384;i+=256) acc+=expf(g_s[i]-M);
  acc=wredsum(acc);
  __syncthreads();
  if(lane==0) sw[w]=acc;
  __syncthreads();
  if(t==0){
    float S=0.f;
    #pragma unroll
    for(int i=0;i<8;i++) S+=sw[i];
    g_red[0]=M; g_red[1]=S;
  }
}

// ---- per-b head on the single selected row ----
__global__ __launch_bounds__(128)
void gnn_k3(const float* __restrict__ fc3_w, const float* __restrict__ fc3_b,
            const float* __restrict__ ln3_g, const float* __restrict__ ln3_b,
            const float* __restrict__ fc4_w, const float* __restrict__ fc4_b,
            const float* __restrict__ ln4_g, const float* __restrict__ ln4_b,
            const int* __restrict__ agent_id, float* __restrict__ out)
{
  __shared__ float shf[128], sy[128], sred[8];
  int b=blockIdx.x, t=threadIdx.x, lane=t&31, w=t>>5;
  shf[t]=g_hfsel[b*128+t];
  __syncthreads();
  float acc=fc3_b[t];
  #pragma unroll 4
  for(int k=0;k<128;k++) acc=fmaf(shf[k],fc3_w[k*128+t],acc);
  float v=fmaxf(acc,0.f);
  float s1=wredsum(v), s2=wredsum(v*v);
  if(lane==0){sred[w]=s1; sred[4+w]=s2;}
  __syncthreads();
  s1=sred[0]+sred[1]+sred[2]+sred[3];
  s2=sred[4]+sred[5]+sred[6]+sred[7];
  float mu=s1*(1.f/128.f);
  float inv=rsqrtf(s2*(1.f/128.f)-mu*mu+1e-5f);
  float vn=(v-mu)*inv*ln3_g[t]+ln3_b[t];
  int ag=agent_id[b];
  float alpha=expf(g_s[b*32+ag]-g_red[0])/g_red[1];
  sy[t]=alpha*vn;
  __syncthreads();
  acc=fc4_b[t];
  #pragma unroll 4
  for(int k=0;k<128;k++) acc=fmaf(sy[k],fc4_w[k*128+t],acc);
  v=fmaxf(acc,0.f);
  s1=wredsum(v); s2=wredsum(v*v);
  __syncthreads();
  if(lane==0){sred[w]=s1; sred[4+w]=s2;}
  __syncthreads();
  s1=sred[0]+sred[1]+sred[2]+sred[3];
  s2=sred[4]+sred[5]+sred[6]+sred[7];
  mu=s1*(1.f/128.f);
  inv=rsqrtf(s2*(1.f/128.f)-mu*mu+1e-5f);
  out[b*128+t]=(v-mu)*inv*ln4_g[t]+ln4_b[t];
}

extern "C" void kernel_launch(void* const* d_in, const int* in_sizes, int n_in,
                              void* d_out, int out_size)
{
  const float* node_obs=(const float*)d_in[0];
  const float* adj     =(const float*)d_in[1];
  const int*   agent_id=(const int*)  d_in[2];
  const float* emb     =(const float*)d_in[3];
  const float* lin1_w  =(const float*)d_in[4];
  const float* lin1_b  =(const float*)d_in[5];
  const float* ln1_g   =(const float*)d_in[6];
  const float* ln1_b   =(const float*)d_in[7];
  const float* linh_w  =(const float*)d_in[8];
  const float* linh_b  =(const float*)d_in[9];
  const float* lnh_g   =(const float*)d_in[10];
  const float* lnh_b   =(const float*)d_in[11];
  const float* fc2a_w  =(const float*)d_in[12];
  const float* fc2a_b  =(const float*)d_in[13];
  const float* fc2b_w  =(const float*)d_in[14];
  const float* fc2b_b  =(const float*)d_in[15];
  const float* fc3_w   =(const float*)d_in[16];
  const float* fc3_b   =(const float*)d_in[17];
  const float* ln3_g   =(const float*)d_in[18];
  const float* ln3_b   =(const float*)d_in[19];
  const float* fc4_w   =(const float*)d_in[20];
  const float* fc4_b   =(const float*)d_in[21];
  const float* ln4_g   =(const float*)d_in[22];
  const float* ln4_b   =(const float*)d_in[23];

  cudaFuncSetAttribute(gnn_k1, cudaFuncAttributeMaxDynamicSharedMemorySize, SMEM_BYTES);

  gnn_k1<<<512,256,SMEM_BYTES>>>(node_obs,adj,agent_id,emb,
                                 lin1_w,lin1_b,ln1_g,ln1_b,
                                 linh_w,linh_b,lnh_g,lnh_b,
                                 fc2a_w,fc2a_b,fc2b_w,fc2b_b);
  gnn_k2<<<1,256>>>();
  gnn_k3<<<512,128>>>(fc3_w,fc3_b,ln3_g,ln3_b,fc4_w,fc4_b,ln4_g,ln4_b,
                      agent_id,(float*)d_out);
}

// round 16
// speedup vs baseline: 1.8133x; 1.1086x over previous
#include <cuda_runtime.h>
#include <cuda_bf16.h>

#define FULLMASK 0xffffffffu

// scratch (allocation-free contract: __device__ globals)
__device__ float g_s[16384];        // softmax logits, one per (b, c)
__device__ float g_hfsel[512*128];  // hf row at agent_id per b
__device__ float g_red[2];          // softmax max, sumexp

__device__ __forceinline__ float wredsum(float v){
  #pragma unroll
  for(int o=16;o;o>>=1) v += __shfl_xor_sync(FULLMASK,v,o);
  return v;
}

__device__ __forceinline__ unsigned smem_u32(const void* p){
  unsigned a;
  asm("{ .reg .u64 t; cvta.to.shared.u64 t, %1; cvt.u32.u64 %0, t; }" : "=r"(a) : "l"(p));
  return a;
}

// ---- warp-level bf16 MMA (baseline PTX, sm_80+; runs on tensor pipe) ----
__device__ __forceinline__ void mma16816(float* d, const unsigned* a, unsigned b0, unsigned b1){
  asm volatile("mma.sync.aligned.m16n8k16.row.col.f32.bf16.bf16.f32 "
    "{%0,%1,%2,%3}, {%4,%5,%6,%7}, {%8,%9}, {%0,%1,%2,%3};"
    : "+f"(d[0]),"+f"(d[1]),"+f"(d[2]),"+f"(d[3])
    : "r"(a[0]),"r"(a[1]),"r"(a[2]),"r"(a[3]), "r"(b0),"r"(b1));
}

// ---- ldmatrix/stmatrix (baseline PTX sm_75+/sm_90+) ----
__device__ __forceinline__ void ldsm4(unsigned* r, unsigned a){
  asm volatile("ldmatrix.sync.aligned.m8n8.x4.shared.b16 {%0,%1,%2,%3}, [%4];"
    : "=r"(r[0]),"=r"(r[1]),"=r"(r[2]),"=r"(r[3]) : "r"(a));
}
__device__ __forceinline__ void ldsm4t(unsigned* r, unsigned a){
  asm volatile("ldmatrix.sync.aligned.m8n8.x4.trans.shared.b16 {%0,%1,%2,%3}, [%4];"
    : "=r"(r[0]),"=r"(r[1]),"=r"(r[2]),"=r"(r[3]) : "r"(a));
}
__device__ __forceinline__ void stsm2(unsigned a, unsigned r0, unsigned r1){
  asm volatile("stmatrix.sync.aligned.m8n8.x2.shared.b16 [%0], {%1,%2};"
    :: "r"(a),"r"(r0),"r"(r1) : "memory");
}

// split x = hi + lo (both bf16), pack adjacent pairs (even elem low half)
__device__ __forceinline__ void splitpair(float a, float b, unsigned &hi, unsigned &lo){
  __nv_bfloat16 ha=__float2bfloat16_rn(a), hb=__float2bfloat16_rn(b);
  __nv_bfloat16 la=__float2bfloat16_rn(a-__bfloat162float(ha));
  __nv_bfloat16 lb=__float2bfloat16_rn(b-__bfloat162float(hb));
  hi=(unsigned)__bfloat16_as_ushort(ha)|((unsigned)__bfloat16_as_ushort(hb)<<16);
  lo=(unsigned)__bfloat16_as_ushort(la)|((unsigned)__bfloat16_as_ushort(lb)<<16);
}

// ---- smem byte layout ----
// W rows [n][k] bf16, stride 136 elems (272B) -> conflict-free frag loads
#define B_WH2 0        // 34816  layer2 W hi
#define B_WL2 34816    // 34816  layer2 W lo
#define B_WH3 69632    // 34816  layer3 W hi
#define B_WL3 104448   // 34816  layer3 W lo
#define B_AH  139264   // 34816  act hi [e][k] (also: compaction scratch, final hacc)
#define B_AL  174080   // 34816  act lo       (also: xj preamble)
#define B_BASE 208896  // 16896  base[r][h] fp32 stride 132 (stage B: biases)
#define B_EL  225792   // 3072   e values (768 floats)
#define B_CL  228864   // 1536   (c<<5)|r shorts (768)
#define B_P1  230400   // 1536   w1row[128], ln1g[128], ln1b[128]
#define SMEM_BYTES 231936

__global__ __launch_bounds__(256,1)
void gnn_k1(const float* __restrict__ node_obs, const float* __restrict__ adj,
            const int* __restrict__ agent_id, const float* __restrict__ emb,
            const float* __restrict__ lin1_w, const float* __restrict__ lin1_b,
            const float* __restrict__ ln1_g, const float* __restrict__ ln1_b,
            const float* __restrict__ linh_w, const float* __restrict__ linh_b,
            const float* __restrict__ lnh_g, const float* __restrict__ lnh_b,
            const float* __restrict__ fc2a_w, const float* __restrict__ fc2a_b,
            const float* __restrict__ fc2b_w, const float* __restrict__ fc2b_b)
{
  extern __shared__ __align__(16) char smc[];
  const int b=blockIdx.x, t=threadIdx.x, lane=t&31, w=t>>5;
  const unsigned sbase = smem_u32(smc);

  int*   scount=(int*)(smc+B_AH);     // scratch aliases act_hi (pre-tile only)
  int*   sstart=scount+32;            // 33 entries
  short* clist=(short*)(smc+B_CL);
  float* elist=(float*)(smc+B_EL);
  float* sxj  =(float*)(smc+B_AL);    // alias, preamble only
  float* sbase_f=(float*)(smc+B_BASE);
  float* p1   =(float*)(smc+B_P1);

  // ---- weights fp32 -> split bf16 hi/lo, [n][k] stride 136 ----
  {
    const float4* src=(const float4*)linh_w;   // [l][k][n]
    for(int i=t;i<8192;i+=256){
      int l=i>>12, rem=i&4095, k=rem>>5, n0=(rem&31)*4;
      float4 v=src[i];
      char* dh=smc+(l?B_WH3:B_WH2);
      char* dl=smc+(l?B_WL3:B_WL2);
      float vv[4]={v.x,v.y,v.z,v.w};
      #pragma unroll
      for(int j=0;j<4;j++){
        unsigned off=(unsigned)(((n0+j)*136+k)*2);
        __nv_bfloat16 h=__float2bfloat16_rn(vv[j]);
        __nv_bfloat16 lo=__float2bfloat16_rn(vv[j]-__bfloat162float(h));
        *(__nv_bfloat16*)(dh+off)=h; *(__nv_bfloat16*)(dl+off)=lo;
      }
    }
  }
  if(t<128){ p1[t]=lin1_w[31*128+t]; p1[128+t]=ln1_g[t]; p1[256+t]=ln1_b[t]; }
  if(t<32){
    const int r=t;
    const float* no=node_obs+(size_t)b*512+r*16;
    #pragma unroll
    for(int k=0;k<15;k++) sxj[r*32+k]=no[k];
    int ent=(int)no[15];
    #pragma unroll
    for(int j=0;j<16;j++) sxj[r*32+15+j]=emb[ent*16+j];
    sxj[r*32+31]=0.f;
  }
  if(t<32) scount[t]=0;
  for(int i=t;i<768;i+=256){ clist[i]=-1; elist[i]=0.f; }
  __syncthreads();

  // ---- base[r][h] = xj[r] @ W1[0:31] + b1 (fp32, stride 132) ----
  {
    const int h=t&127, r0=t>>7;
    float acc[16];
    float bv=lin1_b[h];
    #pragma unroll
    for(int j=0;j<16;j++) acc[j]=bv;
    for(int k=0;k<31;k++){
      float wv=lin1_w[k*128+h];
      #pragma unroll
      for(int j=0;j<16;j++) acc[j]=fmaf(sxj[(r0+2*j)*32+k],wv,acc[j]);
    }
    #pragma unroll
    for(int j=0;j<16;j++) sbase_f[(r0+2*j)*132+h]=acc[j];
  }

  // ---- edge compaction (c-major): 4 edges/thread, c = t>>3 ----
  int nact;
  {
    const float* padj=adj+(size_t)b*1024;
    const int cc=t>>3;
    float ev[4]; int rv[4], av[4]; int cnt=0;
    #pragma unroll
    for(int q=0;q<4;q++){
      int idx=t*4+q, r=idx&31;
      float v=padj[r*32+cc];
      int a=(v>0.f)&&(v<1.0f);
      av[q]=a; ev[q]=v; rv[q]=r; cnt+=a;
    }
    if(cnt) atomicAdd(&scount[cc],cnt);
    int x=cnt;
    #pragma unroll
    for(int o=1;o<32;o<<=1){ int y=__shfl_up_sync(FULLMASK,x,o); if(lane>=o)x+=y; }
    __syncthreads();
    if(t==0){ int run=0;
      #pragma unroll
      for(int c=0;c<32;c++){ sstart[c]=run; run+=scount[c]; }
      sstart[32]=run;
    }
    __syncthreads();
    nact=sstart[32]; if(nact>768)nact=768;
    int pos=sstart[w*4]+x-cnt;
    #pragma unroll
    for(int q=0;q<4;q++){
      if(av[q]&&pos<768){ clist[pos]=(short)((cc<<5)|rv[q]); elist[pos]=ev[q]; pos++; }
    }
    __syncthreads();   // scratch (act area) now dead -> tiles may write act
  }

  const char* actH=smc+B_AH;
  const char* actL=smc+B_AL;
  const unsigned actHu=sbase+B_AH, actLu=sbase+B_AL;
  const int cb=(w&1)*16+(lane>>2);   // agg-mma c row
  const int nt0=(w>>1)*4;            // agg-mma ntile group
  const int col0=(lane&3)*2;

  // ---- precomputed per-lane ldmatrix/stmatrix address offsets ----
  const unsigned aOffA = (unsigned)((16*w+(lane&15))*272 + (lane>>4)*16);
  const unsigned bOff  = (unsigned)((lane&7)*272 + (lane>>3)*16);
  const unsigned sOff  = (unsigned)((16*w+(lane&15))*272);
  const unsigned gOff  = (unsigned)((lane&15)*272 + (nt0*8 + (lane>>4)*8)*2);

  float hD[4][4];
  #pragma unroll
  for(int j=0;j<4;j++){hD[j][0]=0;hD[j][1]=0;hD[j][2]=0;hD[j][3]=0;}

  const int ntiles=(nact+127)>>7;
  for(int T=0;T<ntiles;T++){
    const int tb=T<<7;
    // ===== layer 1: 2 threads per edge (k halves), LN, split -> act =====
    {
      const int el=16*w+(lane>>1);       // warp-local edges match its m-tile
      const int khalf=lane&1;
      const int gi=tb+el;
      short cv=clist[gi];
      int r=cv&31; float e=elist[gi];
      const float4* brow=(const float4*)(sbase_f+r*132+khalf*64);
      const float4* w14=(const float4*)(p1+khalf*64);
      const float4* g14=(const float4*)(p1+128+khalf*64);
      const float4* b14=(const float4*)(p1+256+khalf*64);
      float s=0.f,p=0.f;
      #pragma unroll
      for(int q=0;q<16;q++){
        float4 bs=brow[q], wv=w14[q];
        float v0=fmaxf(fmaf(e,wv.x,bs.x),0.f);
        float v1=fmaxf(fmaf(e,wv.y,bs.y),0.f);
        float v2=fmaxf(fmaf(e,wv.z,bs.z),0.f);
        float v3=fmaxf(fmaf(e,wv.w,bs.w),0.f);
        s+=v0+v1+v2+v3;
        p=fmaf(v0,v0,fmaf(v1,v1,fmaf(v2,v2,fmaf(v3,v3,p))));
      }
      s+=__shfl_xor_sync(FULLMASK,s,1);
      p+=__shfl_xor_sync(FULLMASK,p,1);
      float mu=s*(1.f/128.f);
      float inv=rsqrtf(p*(1.f/128.f)-mu*mu+1e-5f);
      char* dh=(char*)actH+(el*136+khalf*64)*2;
      char* dl=(char*)actL+(el*136+khalf*64)*2;
      #pragma unroll
      for(int q=0;q<16;q++){
        float4 bs=brow[q], wv=w14[q], g=g14[q], bb=b14[q];
        float o0=(fmaxf(fmaf(e,wv.x,bs.x),0.f)-mu)*inv*g.x+bb.x;
        float o1=(fmaxf(fmaf(e,wv.y,bs.y),0.f)-mu)*inv*g.y+bb.y;
        float o2=(fmaxf(fmaf(e,wv.z,bs.z),0.f)-mu)*inv*g.z+bb.z;
        float o3=(fmaxf(fmaf(e,wv.w,bs.w),0.f)-mu)*inv*g.w+bb.w;
        unsigned h0,l0,h1,l1;
        splitpair(o0,o1,h0,l0); splitpair(o2,o3,h1,l1);
        *(uint2*)(dh+q*8)=make_uint2(h0,h1);
        *(uint2*)(dl+q*8)=make_uint2(l0,l1);
      }
    }

    // ===== two hidden layers: warp-local 16x128x128 split-bf16 MMA =====
    #pragma unroll 1
    for(int l=0;l<2;l++){
      __syncwarp();
      float d[16][4];
      #pragma unroll
      for(int n=0;n<16;n++){d[n][0]=0;d[n][1]=0;d[n][2]=0;d[n][3]=0;}
      const unsigned bBaseH = sbase + (l?B_WH3:B_WH2) + bOff;
      const unsigned bBaseL = sbase + (l?B_WL3:B_WL2) + bOff;
      #pragma unroll 1
      for(int kk2=0;kk2<4;kk2++){
        // A frags for this k32 window only (16 regs, not 64)
        unsigned Ah0[4],Ah1[4],Al0[4],Al1[4];
        ldsm4(Ah0, actHu + aOffA + (2*kk2  )*32);
        ldsm4(Ah1, actHu + aOffA + (2*kk2+1)*32);
        ldsm4(Al0, actLu + aOffA + (2*kk2  )*32);
        ldsm4(Al1, actLu + aOffA + (2*kk2+1)*32);
        // software-pipelined B frags (double buffer)
        unsigned bh[2][4], bl[2][4];
        ldsm4(bh[0], bBaseH + kk2*64);
        ldsm4(bl[0], bBaseL + kk2*64);
        #pragma unroll
        for(int nt=0;nt<16;nt++){
          const int cur=nt&1, nxt=cur^1;
          if(nt<15){
            ldsm4(bh[nxt], bBaseH + (nt+1)*2176 + kk2*64);
            ldsm4(bl[nxt], bBaseL + (nt+1)*2176 + kk2*64);
          }
          mma16816(d[nt],Ah0,bh[cur][0],bh[cur][1]);
          mma16816(d[nt],Al0,bh[cur][0],bh[cur][1]);
          mma16816(d[nt],Ah0,bl[cur][0],bl[cur][1]);
          mma16816(d[nt],Ah1,bh[cur][2],bh[cur][3]);
          mma16816(d[nt],Al1,bh[cur][2],bh[cur][3]);
          mma16816(d[nt],Ah1,bl[cur][2],bl[cur][3]);
        }
      }
      // epilogue: bias+relu+LN (rows r0=16w+(lane>>2), r1=r0+8), split -> act
      const float* lhbg=linh_b+l*128;
      float2 bias[16];
      #pragma unroll
      for(int n=0;n<16;n++) bias[n]=*(const float2*)(lhbg+n*8+col0);
      float s0=0,p0=0,s1=0,q1=0;
      #pragma unroll
      for(int n=0;n<16;n++){
        float v0=fmaxf(d[n][0]+bias[n].x,0.f);
        float v1=fmaxf(d[n][1]+bias[n].y,0.f);
        float v2=fmaxf(d[n][2]+bias[n].x,0.f);
        float v3=fmaxf(d[n][3]+bias[n].y,0.f);
        s0+=v0+v1; p0=fmaf(v0,v0,fmaf(v1,v1,p0));
        s1+=v2+v3; q1=fmaf(v2,v2,fmaf(v3,v3,q1));
      }
      #pragma unroll
      for(int o=1;o<4;o<<=1){
        s0+=__shfl_xor_sync(FULLMASK,s0,o);
        p0+=__shfl_xor_sync(FULLMASK,p0,o);
        s1+=__shfl_xor_sync(FULLMASK,s1,o);
        q1+=__shfl_xor_sync(FULLMASK,q1,o);
      }
      float mu0=s0*(1.f/128.f), inv0=rsqrtf(p0*(1.f/128.f)-mu0*mu0+1e-5f);
      float mu1=s1*(1.f/128.f), inv1=rsqrtf(q1*(1.f/128.f)-mu1*mu1+1e-5f);
      const float* gg=lnh_g+l*128;
      const float* b2g=lnh_b+l*128;
      #pragma unroll
      for(int n=0;n<16;n++){
        float2 g=*(const float2*)(gg+n*8+col0);
        float2 b2=*(const float2*)(b2g+n*8+col0);
        float o0=(fmaxf(d[n][0]+bias[n].x,0.f)-mu0)*inv0*g.x+b2.x;
        float o1=(fmaxf(d[n][1]+bias[n].y,0.f)-mu0)*inv0*g.y+b2.y;
        float o2=(fmaxf(d[n][2]+bias[n].x,0.f)-mu1)*inv1*g.x+b2.x;
        float o3=(fmaxf(d[n][3]+bias[n].y,0.f)-mu1)*inv1*g.y+b2.y;
        unsigned h0,l0,h1,l1;
        splitpair(o0,o1,h0,l0); splitpair(o2,o3,h1,l1);
        stsm2(actHu + sOff + n*16, h0,h1);
        stsm2(actLu + sOff + n*16, l0,l1);
      }
    }

    // ===== aggregation: h += sel(c,e) @ m via MMA (sel exact 0/1) =====
    __syncthreads();
    #pragma unroll 1
    for(int kk=0;kk<8;kk++){
      int e0=tb+kk*16+col0;   // global index into clist
      int c0v=clist[e0]>>5, c1v=clist[e0+1]>>5;
      int c2v=clist[e0+8]>>5, c3v=clist[e0+9]>>5;
      unsigned A[4];
      A[0]=(c0v==cb  ?0x3F80u:0u)|((c1v==cb  )?0x3F800000u:0u);
      A[1]=(c0v==cb+8?0x3F80u:0u)|((c1v==cb+8)?0x3F800000u:0u);
      A[2]=(c2v==cb  ?0x3F80u:0u)|((c3v==cb  )?0x3F800000u:0u);
      A[3]=(c2v==cb+8?0x3F80u:0u)|((c3v==cb+8)?0x3F800000u:0u);
      unsigned bhA[4],bhB[4],blA[4],blB[4];
      unsigned gh = actHu + gOff + kk*4352;
      unsigned gl2= actLu + gOff + kk*4352;
      ldsm4t(bhA, gh);     ldsm4t(bhB, gh+32);
      ldsm4t(blA, gl2);    ldsm4t(blB, gl2+32);
      mma16816(hD[0],A,bhA[0],bhA[1]); mma16816(hD[0],A,blA[0],blA[1]);
      mma16816(hD[1],A,bhA[2],bhA[3]); mma16816(hD[1],A,blA[2],blA[3]);
      mma16816(hD[2],A,bhB[0],bhB[1]); mma16816(hD[2],A,blB[0],blB[1]);
      mma16816(hD[3],A,bhB[2],bhB[3]); mma16816(hD[3],A,blB[2],blB[3]);
    }
    __syncthreads();   // agg reads done before next tile's layer-1 writes
  }

  // ---- write h to smem (act region dead) ----
  float* hacc=(float*)(smc+B_AH);
  __syncthreads();
  #pragma unroll
  for(int j=0;j<4;j++){
    int col=(nt0+j)*8+col0;
    hacc[cb*132+col]  =hD[j][0];
    hacc[cb*132+col+1]=hD[j][1];
    hacc[(cb+8)*132+col]  =hD[j][2];
    hacc[(cb+8)*132+col+1]=hD[j][3];
  }
  __syncthreads();

  // ---- stage B: s[b,c] = relu(h @ fc2a + b2a) @ fc2b + b2b ----
  float* w2s=(float*)(smc+B_WH2);
  {
    const float4* s2=(const float4*)fc2a_w; float4* d2=(float4*)w2s;
    for(int i=t;i<4096;i+=256) d2[i]=s2[i];
    float* bb=(float*)(smc+B_BASE);
    if(t<128){ bb[t]=fc2a_b[t]; bb[128+t]=fc2b_w[t]; }
  }
  __syncthreads();
  {
    const float* bb=(const float*)(smc+B_BASE);
    float4 b2=((const float4*)bb)[lane];
    float4 f2=((const float4*)(bb+128))[lane];
    float acc[4][4];
    #pragma unroll
    for(int cc=0;cc<4;cc++){acc[cc][0]=b2.x;acc[cc][1]=b2.y;acc[cc][2]=b2.z;acc[cc][3]=b2.w;}
    const int c0=w*4;
    #pragma unroll 4
    for(int k=0;k<128;k++){
      float4 wv=((const float4*)w2s)[k*32+lane];
      #pragma unroll
      for(int cc=0;cc<4;cc++){
        float a=hacc[(c0+cc)*132+k];
        acc[cc][0]=fmaf(a,wv.x,acc[cc][0]);
        acc[cc][1]=fmaf(a,wv.y,acc[cc][1]);
        acc[cc][2]=fmaf(a,wv.z,acc[cc][2]);
        acc[cc][3]=fmaf(a,wv.w,acc[cc][3]);
      }
    }
    float b2b=fc2b_b[0];
    #pragma unroll
    for(int cc=0;cc<4;cc++){
      float p=fmaxf(acc[cc][0],0.f)*f2.x+fmaxf(acc[cc][1],0.f)*f2.y
             +fmaxf(acc[cc][2],0.f)*f2.z+fmaxf(acc[cc][3],0.f)*f2.w;
      p=wredsum(p);
      if(lane==0) g_s[b*32+c0+cc]=p+b2b;
    }
  }
  if(t<128){
    int ag=agent_id[b];
    g_hfsel[b*128+t]=hacc[ag*132+t];
  }
}

// ---- global softmax reduction over 16384 logits ----
__global__ void gnn_k2(){
  __shared__ float sw[8];
  int t=threadIdx.x, lane=t&31, w=t>>5;
  float m=-3.4e38f;
  for(int i=t;i<16384;i+=256) m=fmaxf(m,g_s[i]);
  #pragma unroll
  for(int o=16;o;o>>=1) m=fmaxf(m,__shfl_xor_sync(FULLMASK,m,o));
  if(lane==0) sw[w]=m;
  __syncthreads();
  float M=sw[0];
  #pragma unroll
  for(int i=1;i<8;i++) M=fmaxf(M,sw[i]);
  float acc=0.f;
  for(int i=t;i<16384;i+=256) acc+=expf(g_s[i]-M);
  acc=wredsum(acc);
  __syncthreads();
  if(lane==0) sw[w]=acc;
  __syncthreads();
  if(t==0){
    float S=0.f;
    #pragma unroll
    for(int i=0;i<8;i++) S+=sw[i];
    g_red[0]=M; g_red[1]=S;
  }
}

// ---- per-b head on the single selected row ----
__global__ __launch_bounds__(128)
void gnn_k3(const float* __restrict__ fc3_w, const float* __restrict__ fc3_b,
            const float* __restrict__ ln3_g, const float* __restrict__ ln3_b,
            const float* __restrict__ fc4_w, const float* __restrict__ fc4_b,
            const float* __restrict__ ln4_g, const float* __restrict__ ln4_b,
            const int* __restrict__ agent_id, float* __restrict__ out)
{
  __shared__ float shf[128], sy[128], sred[8];
  int b=blockIdx.x, t=threadIdx.x, lane=t&31, w=t>>5;
  shf[t]=g_hfsel[b*128+t];
  __syncthreads();
  float acc=fc3_b[t];
  #pragma unroll 4
  for(int k=0;k<128;k++) acc=fmaf(shf[k],fc3_w[k*128+t],acc);
  float v=fmaxf(acc,0.f);
  float s1=wredsum(v), s2=wredsum(v*v);
  if(lane==0){sred[w]=s1; sred[4+w]=s2;}
  __syncthreads();
  s1=sred[0]+sred[1]+sred[2]+sred[3];
  s2=sred[4]+sred[5]+sred[6]+sred[7];
  float mu=s1*(1.f/128.f);
  float inv=rsqrtf(s2*(1.f/128.f)-mu*mu+1e-5f);
  float vn=(v-mu)*inv*ln3_g[t]+ln3_b[t];
  int ag=agent_id[b];
  float alpha=expf(g_s[b*32+ag]-g_red[0])/g_red[1];
  sy[t]=alpha*vn;
  __syncthreads();
  acc=fc4_b[t];
  #pragma unroll 4
  for(int k=0;k<128;k++) acc=fmaf(sy[k],fc4_w[k*128+t],acc);
  v=fmaxf(acc,0.f);
  s1=wredsum(v); s2=wredsum(v*v);
  __syncthreads();
  if(lane==0){sred[w]=s1; sred[4+w]=s2;}
  __syncthreads();
  s1=sred[0]+sred[1]+sred[2]+sred[3];
  s2=sred[4]+sred[5]+sred[6]+sred[7];
  mu=s1*(1.f/128.f);
  inv=rsqrtf(s2*(1.f/128.f)-mu*mu+1e-5f);
  out[b*128+t]=(v-mu)*inv*ln4_g[t]+ln4_b[t];
}

extern "C" void kernel_launch(void* const* d_in, const int* in_sizes, int n_in,
                              void* d_out, int out_size)
{
  const float* node_obs=(const float*)d_in[0];
  const float* adj     =(const float*)d_in[1];
  const int*   agent_id=(const int*)  d_in[2];
  const float* emb     =(const float*)d_in[3];
  const float* lin1_w  =(const float*)d_in[4];
  const float* lin1_b  =(const float*)d_in[5];
  const float* ln1_g   =(const float*)d_in[6];
  const float* ln1_b   =(const float*)d_in[7];
  const float* linh_w  =(const float*)d_in[8];
  const float* linh_b  =(const float*)d_in[9];
  const float* lnh_g   =(const float*)d_in[10];
  const float* lnh_b   =(const float*)d_in[11];
  const float* fc2a_w  =(const float*)d_in[12];
  const float* fc2a_b  =(const float*)d_in[13];
  const float* fc2b_w  =(const float*)d_in[14];
  const float* fc2b_b  =(const float*)d_in[15];
  const float* fc3_w   =(const float*)d_in[16];
  const float* fc3_b   =(const float*)d_in[17];
  const float* ln3_g   =(const float*)d_in[18];
  const float* ln3_b   =(const float*)d_in[19];
  const float* fc4_w   =(const float*)d_in[20];
  const float* fc4_b   =(const float*)d_in[21];
  const float* ln4_g   =(const float*)d_in[22];
  const float* ln4_b   =(const float*)d_in[23];

  cudaFuncSetAttribute(gnn_k1, cudaFuncAttributeMaxDynamicSharedMemorySize, SMEM_BYTES);

  gnn_k1<<<512,256,SMEM_BYTES>>>(node_obs,adj,agent_id,emb,
                                 lin1_w,lin1_b,ln1_g,ln1_b,
                                 linh_w,linh_b,lnh_g,lnh_b,
                                 fc2a_w,fc2a_b,fc2b_w,fc2b_b);
  gnn_k2<<<1,256>>>();
  gnn_k3<<<512,128>>>(fc3_w,fc3_b,ln3_g,ln3_b,fc4_w,fc4_b,ln4_g,ln4_b,
                      agent_id,(float*)d_out);
}